// round 7
// baseline (speedup 1.0000x reference)
#include <cuda_runtime.h>
#include <cuda_fp16.h>
#include <math.h>
#include <stdint.h>

#define B_   64
#define S_   512
#define P_   32
#define L_   30
#define H_   768
#define FH_  1024
#define MROWS (B_*P_)   // 2048
#define KP   16         // pp partial planes

// ======================= device scratch (no allocation) =======================
__device__ __half g_W1h[FH_ * H_];          // W1[:768]^T hi plane [1024,768]
__device__ __half g_W1l[FH_ * H_];          // lo plane
__device__ float g_W23[FH_ * 32];           // W2@W3 padded [1024][32]
__device__ float g_b23[32];                 // b2@W3 + b3, padded
__device__ float g_h1[MROWS * FH_];         // [2048,1024] fp32
__device__ float g_pp[B_ * FH_];            // pooler@W1[768:]+b1
__device__ float g_ppp[KP][B_ * FH_];       // split-K partials
__device__ float g_part[256 * 5];

// ======================= helpers =======================
__device__ __forceinline__ uint32_t smem_u32(const void* p) {
    uint32_t a;
    asm("{ .reg .u64 t; cvta.to.shared.u64 t, %1; cvt.u32.u64 %0, t; }"
        : "=r"(a) : "l"(p));
    return a;
}
#define CP16(dst_u32, src_ptr) \
    asm volatile("cp.async.cg.shared.global [%0], [%1], 16;" \
        :: "r"(dst_u32), "l"(src_ptr))
#define CP_COMMIT() asm volatile("cp.async.commit_group;")
#define CP_WAIT1()  asm volatile("cp.async.wait_group 1;")
#define CP_WAIT0()  asm volatile("cp.async.wait_group 0;")

// split float2 -> packed half2 hi + half2 lo
__device__ __forceinline__ void f2h_split(float2 x, uint32_t& hi, uint32_t& lo) {
    __half2 h = __float22half2_rn(x);
    float2 hf = __half22float2(h);
    __half2 l = __float22half2_rn(make_float2(x.x - hf.x, x.y - hf.y));
    hi = *reinterpret_cast<uint32_t*>(&h);
    lo = *reinterpret_cast<uint32_t*>(&l);
}

__device__ __forceinline__ void mma_f16(float* d, const uint32_t* a,
                                        uint32_t b0, uint32_t b1) {
    asm volatile(
        "mma.sync.aligned.m16n8k16.row.col.f32.f16.f16.f32 "
        "{%0,%1,%2,%3}, {%4,%5,%6,%7}, {%8,%9}, {%0,%1,%2,%3};"
        : "+f"(d[0]), "+f"(d[1]), "+f"(d[2]), "+f"(d[3])
        : "r"(a[0]), "r"(a[1]), "r"(a[2]), "r"(a[3]), "r"(b0), "r"(b1));
}

// ======================= pre-pass kernels =======================
// transpose + fp16-split: src[KK,NN] -> hi/lo half planes at [NN,KK]
template<int KK, int NN>
__global__ __launch_bounds__(256) void k_Tsplit(const float* __restrict__ src,
                                                __half* __restrict__ dh,
                                                __half* __restrict__ dl) {
    __shared__ float t[32][33];
    int n0 = blockIdx.x * 32, k0 = blockIdx.y * 32;
    int tx = threadIdx.x, ty = threadIdx.y;
#pragma unroll
    for (int j = 0; j < 4; j++)
        t[ty + 8 * j][tx] = src[(size_t)(k0 + ty + 8 * j) * NN + n0 + tx];
    __syncthreads();
#pragma unroll
    for (int j = 0; j < 4; j++) {
        int n = n0 + ty + 8 * j;
        int k = k0 + tx;
        float x = t[tx][ty + 8 * j];
        __half h = __float2half_rn(x);
        __half l = __float2half_rn(x - __half2float(h));
        dh[(size_t)n * KK + k] = h;
        dl[(size_t)n * KK + k] = l;
    }
}

// ---------- W23 = W2 @ W3 (+b23) ----------
// grid 128, block 256: warp per k1 row (8 rows/CTA), lane = output col
__global__ __launch_bounds__(256) void k_w23(const float* __restrict__ W2,
                                             const float* __restrict__ W3,
                                             const float* __restrict__ b2,
                                             const float* __restrict__ b3) {
    __shared__ float w3s[512][32];           // 64KB padded
    const int tid = threadIdx.x;
    // stage W3 [512][30] -> padded smem
    for (int idx = tid; idx < 512 * 32; idx += 256) {
        int k2 = idx >> 5, l = idx & 31;
        w3s[k2][l] = (l < L_) ? W3[k2 * L_ + l] : 0.f;
    }
    __syncthreads();
    const int wid = tid >> 5, lane = tid & 31;
    const int k1 = blockIdx.x * 8 + wid;
    const float* w2row = W2 + (size_t)k1 * (FH_ / 2);
    float acc = 0.f;
#pragma unroll 8
    for (int k2 = 0; k2 < FH_ / 2; k2++)
        acc = fmaf(w2row[k2], w3s[k2][lane], acc);
    g_W23[k1 * 32 + lane] = acc;

    if (blockIdx.x == 0 && wid == 0) {
        float bacc = (lane < L_) ? b3[lane] : 0.f;
#pragma unroll 8
        for (int k2 = 0; k2 < FH_ / 2; k2++)
            bacc = fmaf(b2[k2], w3s[k2][lane], bacc);
        g_b23[lane] = bacc;
    }
}

// ---------- split-K pooler GEMM, zero-redundancy loads ----------
// grid (FH/128=8, 8), block 256: thread = 1 col x 64 rows, ky halves 96-K chunk
__global__ __launch_bounds__(256) void k_pp_part(const float* __restrict__ pooler,
                                                 const float* __restrict__ W1) {
    __shared__ float a[B_][96];
    const int ks = blockIdx.y;
    const int colBase = blockIdx.x * 128;
    const int tid = threadIdx.x;
    const int col = colBase + (tid & 127);
    const int ky = tid >> 7;                 // 0/1

    for (int idx = tid; idx < B_ * 96; idx += 256) {
        int row = idx / 96, kk = idx % 96;
        a[row][kk] = pooler[(size_t)row * H_ + ks * 96 + kk];
    }
    __syncthreads();

    const float* wp = W1 + (size_t)(H_ + ks * 96 + ky * 48) * FH_ + col;
    float acc[B_];
#pragma unroll
    for (int r = 0; r < B_; r++) acc[r] = 0.f;
#pragma unroll
    for (int kk = 0; kk < 48; kk++) {
        float w = wp[(size_t)kk * FH_];
#pragma unroll
        for (int r = 0; r < B_; r++)
            acc[r] = fmaf(a[r][ky * 48 + kk], w, acc[r]);
    }
    float* out = g_ppp[ks * 2 + ky];
#pragma unroll
    for (int r = 0; r < B_; r++)
        out[(size_t)r * FH_ + col] = acc[r];
}

// fixed-order reduce of KP partials + b1 -> g_pp
__global__ __launch_bounds__(256) void k_pp_reduce(const float* __restrict__ b1) {
    int i4 = blockIdx.x * 256 + threadIdx.x;          // float4 index
    int col = (i4 * 4) % FH_;
    float4 s = make_float4(0.f, 0.f, 0.f, 0.f);
#pragma unroll
    for (int ks = 0; ks < KP; ks++) {
        float4 v = *(const float4*)&g_ppp[ks][(size_t)i4 * 4];
        s.x += v.x; s.y += v.y; s.z += v.z; s.w += v.w;
    }
    float4 bb = *(const float4*)&b1[col];
    s.x += bb.x; s.y += bb.y; s.z += bb.z; s.w += bb.w;
    *(float4*)&g_pp[(size_t)i4 * 4] = s;
}

// ======================= fp16x3 mma.sync GEMM (B pre-split) =======================
// h1[2048,1024] = gather(te) @ W1^T + pp[b]   (BM=128,BN=128,K=768)
__global__ __launch_bounds__(256) void mma_gemm(
    const float* __restrict__ Asrc, const int* __restrict__ pos,
    const __half* __restrict__ Bh, const __half* __restrict__ Bl,
    float* __restrict__ Cout, const float* __restrict__ addv)
{
    constexpr int BM  = 128;
    constexpr int BN  = 128;
    constexpr int K   = H_;
    constexpr int NIT = K / 32;
    constexpr int LDO = FH_;
    constexpr int MT  = 2;
    constexpr int BCH = 4;                       // B CP16 per thread
    constexpr int ABUF = 128 * 36;               // floats per A buffer
    constexpr int BPLANE = BN * 40;              // halves per plane
    constexpr int BBUFB = 2 * BPLANE * 2;        // bytes per B buffer (2 planes)

    extern __shared__ float sm[];
    float* AsB = sm;                              // [2][ABUF] fp32
    char*  BsBase = (char*)(sm + 2 * ABUF);       // [2][2 planes][BN][40] half

    const int tid = threadIdx.x, wid = tid >> 5, lane = tid & 31;
    const int rowBase = blockIdx.y * BM, colBase = blockIdx.x * BN;
    const int warpRow = (wid & 3) * 32;
    const int warpCol = (wid >> 2) * 64;

    const float* aptr[4];
    int arow[4];
#pragma unroll
    for (int j = 0; j < 4; j++) {
        int r = (tid >> 3) + j * 32;
        arow[j] = r;
        int gr = rowBase + r;
        aptr[j] = Asrc + ((size_t)(gr >> 5) * S_ + pos[gr]) * H_;
    }
    const int acol = (tid & 7) * 4;

    const __half* bsrc[4];
    uint32_t bsmo[4];
#pragma unroll
    for (int j = 0; j < BCH; j++) {
        int ci = tid + j * 256;
        int plane = ci / (BN * 4);
        int rem = ci % (BN * 4);
        int row = rem >> 2, ch = rem & 3;
        const __half* gp = plane ? Bl : Bh;
        bsrc[j] = gp + (size_t)(colBase + row) * K + ch * 8;
        bsmo[j] = (uint32_t)(plane * BPLANE + row * 40 + ch * 8) * 2;
    }
    const uint32_t smA = smem_u32(AsB), smB = smem_u32(BsBase);

    float acc[MT][8][4];
#pragma unroll
    for (int mt = 0; mt < MT; mt++)
#pragma unroll
        for (int nt = 0; nt < 8; nt++)
#pragma unroll
            for (int e = 0; e < 4; e++) acc[mt][nt][e] = 0.f;

#define STAGE(buf, k0) do { \
    uint32_t sa = smA + (buf) * (ABUF * 4); \
    _Pragma("unroll") \
    for (int j = 0; j < 4; j++) \
        CP16(sa + (uint32_t)(arow[j] * 36 + acol) * 4, aptr[j] + (k0) + acol); \
    uint32_t sbp = smB + (buf) * BBUFB; \
    _Pragma("unroll") \
    for (int j = 0; j < BCH; j++) \
        CP16(sbp + bsmo[j], bsrc[j] + (k0)); \
    CP_COMMIT(); \
} while (0)

    STAGE(0, 0);
    for (int it = 0; it < NIT; ++it) {
        if (it + 1 < NIT) { STAGE((it + 1) & 1, (it + 1) * 32); CP_WAIT1(); }
        else              { CP_WAIT0(); }
        __syncthreads();
        const float*  As  = AsB + (it & 1) * ABUF;
        const __half* BsH = (const __half*)(BsBase + (it & 1) * BBUFB);
        const __half* BsL = BsH + BPLANE;
#pragma unroll
        for (int c16 = 0; c16 < 2; c16++) {
            const int kk = c16 * 16 + (lane & 3) * 2;
            uint32_t ah[MT][4], al[MT][4];
#pragma unroll
            for (int mt = 0; mt < MT; mt++) {
                int r0 = warpRow + mt * 16 + (lane >> 2);
                float2 x0 = *(const float2*)&As[r0 * 36 + kk];
                float2 x1 = *(const float2*)&As[(r0 + 8) * 36 + kk];
                float2 x2 = *(const float2*)&As[r0 * 36 + kk + 8];
                float2 x3 = *(const float2*)&As[(r0 + 8) * 36 + kk + 8];
                f2h_split(x0, ah[mt][0], al[mt][0]);
                f2h_split(x1, ah[mt][1], al[mt][1]);
                f2h_split(x2, ah[mt][2], al[mt][2]);
                f2h_split(x3, ah[mt][3], al[mt][3]);
            }
#pragma unroll
            for (int nt = 0; nt < 8; nt++) {
                int n0 = warpCol + nt * 8 + (lane >> 2);
                uint32_t bh0 = *(const uint32_t*)&BsH[n0 * 40 + kk];
                uint32_t bh1 = *(const uint32_t*)&BsH[n0 * 40 + kk + 8];
                uint32_t bl0 = *(const uint32_t*)&BsL[n0 * 40 + kk];
                uint32_t bl1 = *(const uint32_t*)&BsL[n0 * 40 + kk + 8];
#pragma unroll
                for (int mt = 0; mt < MT; mt++) {
                    mma_f16(acc[mt][nt], ah[mt], bh0, bh1);   // a0*b0
                    mma_f16(acc[mt][nt], al[mt], bh0, bh1);   // a1*b0
                    mma_f16(acc[mt][nt], ah[mt], bl0, bl1);   // a0*b1
                }
            }
        }
        __syncthreads();
    }
#undef STAGE

#pragma unroll
    for (int mt = 0; mt < MT; mt++) {
#pragma unroll
        for (int nt = 0; nt < 8; nt++) {
            int r0 = rowBase + warpRow + mt * 16 + (lane >> 2);
            int c  = colBase + warpCol + nt * 8 + (lane & 3) * 2;
            float2 v0 = make_float2(acc[mt][nt][0], acc[mt][nt][1]);
            float2 v1 = make_float2(acc[mt][nt][2], acc[mt][nt][3]);
            float2 p0 = *(const float2*)&addv[(size_t)(r0 >> 5) * FH_ + c];
            float2 p1 = *(const float2*)&addv[(size_t)((r0 + 8) >> 5) * FH_ + c];
            v0.x += p0.x; v0.y += p0.y; v1.x += p1.x; v1.y += p1.y;
            *(float2*)&Cout[(size_t)r0 * LDO + c]       = v0;
            *(float2*)&Cout[(size_t)(r0 + 8) * LDO + c] = v1;
        }
    }
}

// ======================= fused logits + loss =======================
// grid 256, block 256 (8 warps, 1 row each). W23 + 8 h1 rows in smem.
__global__ __launch_bounds__(256) void k_loss2(const float* __restrict__ labels)
{
    extern __shared__ float ls[];
    float* W23s = ls;                 // [1024][32]  = 32768 floats
    float* Hs   = ls + FH_ * 32;      // [8][1024]   =  8192 floats

    const int tid = threadIdx.x;
    const int wid = tid >> 5, lane = tid & 31;
    const int r = blockIdx.x * 8 + wid;

    // stage W23 (coalesced float4)
    const float4* wsrc = (const float4*)g_W23;
    float4* wdst = (float4*)W23s;
    for (int idx = tid; idx < FH_ * 32 / 4; idx += 256)
        wdst[idx] = wsrc[idx];
    // stage this warp's h1 row
    {
        const float4* hsrc = (const float4*)(g_h1 + (size_t)r * FH_);
        float4* hdst = (float4*)(Hs + wid * FH_);
#pragma unroll
        for (int j = 0; j < 8; j++)
            hdst[lane + j * 32] = hsrc[lane + j * 32];
    }
    __syncthreads();

    const float* hrow = Hs + wid * FH_;
    float acc = 0.f;
#pragma unroll 16
    for (int k = 0; k < FH_; k++)
        acc = fmaf(hrow[k], W23s[k * 32 + lane], acc);

    const bool active = (lane < L_);
    float x = acc + g_b23[lane];
    float y = active ? labels[(size_t)r * L_ + lane] : -1.0f;

    unsigned ball_bin  = __ballot_sync(0xffffffffu, active && (x > 0.f));
    unsigned ball_one  = __ballot_sync(0xffffffffu, active && (y > 0.5f));
    unsigned ball_real = __ballot_sync(0xffffffffu, active && (y != -1.0f));

    float sp  = fmaxf(x, 0.f) + log1pf(expf(-fabsf(x)));
    float bce = active ? (sp - x * y) : 0.f;
#pragma unroll
    for (int o = 16; o; o >>= 1) bce += __shfl_xor_sync(0xffffffffu, bce, o);

    __shared__ float sml[8][5];
    if (lane == 0) {
        float mf = (ball_real != 0u) ? 1.f : 0.f;
        int co = __popc(ball_bin);
        int cl = __popc(ball_one);
        float cd = (float)(co - cl);
        bool eq = (mf != 0.f) && (co == 1) && (cl == 1);
        float pd = eq ? (float)(__ffs(ball_bin) - __ffs(ball_one)) : 0.f;
        sml[wid][0] = mf * bce;
        sml[wid][1] = mf;
        sml[wid][2] = mf * cd * cd;
        sml[wid][3] = pd * pd;
        sml[wid][4] = eq ? 1.f : 0.f;
    }
    __syncthreads();
    if (tid < 5) {
        float s = 0.f;
        for (int w = 0; w < 8; w++) s += sml[w][tid];
        g_part[blockIdx.x * 5 + tid] = s;
    }
}

__global__ __launch_bounds__(256)
void k_final(float* __restrict__ out, int out_size)
{
    __shared__ float smf[256][5];
    int t = threadIdx.x;
    for (int c = 0; c < 5; c++) smf[t][c] = g_part[t * 5 + c];
    __syncthreads();
    for (int s = 128; s > 0; s >>= 1) {
        if (t < s)
            for (int c = 0; c < 5; c++) smf[t][c] += smf[t + s][c];
        __syncthreads();
    }
    if (t == 0) {
        float bce_loss   = smf[0][0] / (smf[0][1] * (float)L_);
        float count_loss = smf[0][2] / (float)MROWS;
        float pos_loss   = (smf[0][4] > 0.f) ? (smf[0][3] / smf[0][4]) : 0.f;
        float loss = bce_loss + 10.f * count_loss + 5.f * pos_loss;
        for (int i = 0; i < out_size; i++) out[i] = loss;
    }
}

// ======================= launch =======================
extern "C" void kernel_launch(void* const* d_in, const int* in_sizes, int n_in,
                              void* d_out, int out_size)
{
    const float* te   = (const float*)d_in[0];
    const float* pool = (const float*)d_in[1];
    const int*   pos  = (const int*)  d_in[2];
    const float* lab  = (const float*)d_in[3];
    const float* W1   = (const float*)d_in[4];
    const float* b1   = (const float*)d_in[5];
    const float* W2   = (const float*)d_in[6];
    const float* b2   = (const float*)d_in[7];
    const float* W3   = (const float*)d_in[8];
    const float* b3   = (const float*)d_in[9];

    __half *w1h, *w1l;
    float *h1, *pp;
    cudaGetSymbolAddress((void**)&w1h, g_W1h);
    cudaGetSymbolAddress((void**)&w1l, g_W1l);
    cudaGetSymbolAddress((void**)&h1,  g_h1);
    cudaGetSymbolAddress((void**)&pp,  g_pp);

    const int SM0 = (2 * 128 * 36) * 4 + 2 * (2 * 128 * 40) * 2;  // 77824
    const int SML = (FH_ * 32 + 8 * FH_) * 4;                     // 163840
    cudaFuncSetAttribute(mma_gemm, cudaFuncAttributeMaxDynamicSharedMemorySize, SM0);
    cudaFuncSetAttribute(k_loss2,  cudaFuncAttributeMaxDynamicSharedMemorySize, SML);

    // pre-passes
    k_Tsplit<H_, FH_><<<dim3(FH_ / 32, H_ / 32), dim3(32, 8)>>>(W1, w1h, w1l);
    k_w23<<<FH_ / 8, 256>>>(W2, W3, b2, b3);
    k_pp_part<<<dim3(FH_ / 128, 8), 256>>>(pool, W1);
    k_pp_reduce<<<(B_ * FH_ / 4) / 256, 256>>>(b1);

    // tensor-core GEMM1 (fp16x3 emulated fp32)
    mma_gemm<<<dim3(FH_ / 128, MROWS / 128), 256, SM0>>>(te, pos, w1h, w1l, h1, pp);

    // fused logits + loss, then final reduce
    k_loss2<<<MROWS / 8, 256, SML>>>(lab);
    k_final<<<1, 256>>>((float*)d_out, out_size);
}

// round 8
// speedup vs baseline: 1.0857x; 1.0857x over previous
#include <cuda_runtime.h>
#include <math.h>
#include <stdint.h>

#define B_   64
#define S_   512
#define P_   32
#define L_   30
#define H_   768
#define FH_  1024
#define MROWS (B_*P_)   // 2048

// ======================= device scratch (no allocation) =======================
__device__ float g_W23[FH_ * 32];      // W2@W3, padded cols  [1024][32]
__device__ float g_Wc[2 * H_ * 32];    // W1@W23              [1536][32]
__device__ float g_b23[32];            // b2@W3 + b3
__device__ float g_bc[32];             // b1@W23 + b23
__device__ float g_pq[B_ * 32];        // pooler@Wc_bot + bc  [64][32]
__device__ float g_part[128 * 5];

// ======================= stage 1: W23 = W2 @ W3 (+b23) =======================
// grid 64 x 512thr: 16 rows/CTA, warp = 1 row
__global__ __launch_bounds__(512) void k_w23(const float* __restrict__ W2,
                                             const float* __restrict__ W3,
                                             const float* __restrict__ b2,
                                             const float* __restrict__ b3) {
    extern __shared__ float s[];
    float* w3s = s;                  // [512*32]
    float* w2s = s + 512 * 32;       // [16*512]
    float* b2s = w2s + 16 * 512;     // [512]
    const int tid = threadIdx.x;

    for (int idx = tid; idx < 512 * 32; idx += 512) {
        int k2 = idx >> 5, l = idx & 31;
        w3s[idx] = (l < L_) ? W3[k2 * L_ + l] : 0.f;
    }
    const int row0 = blockIdx.x * 16;
    {
        float4* d = (float4*)w2s;
        const float4* g = (const float4*)(W2 + (size_t)row0 * 512);
        for (int idx = tid; idx < 16 * 512 / 4; idx += 512) d[idx] = g[idx];
    }
    if (tid < 128) ((float4*)b2s)[tid] = ((const float4*)b2)[tid];
    __syncthreads();

    const int wid = tid >> 5, lane = tid & 31;
    const float* arow = w2s + wid * 512;
    float acc = 0.f;
#pragma unroll 4
    for (int k = 0; k < 512; k += 4) {
        float4 a4 = *(const float4*)&arow[k];
        acc = fmaf(a4.x, w3s[(k + 0) * 32 + lane], acc);
        acc = fmaf(a4.y, w3s[(k + 1) * 32 + lane], acc);
        acc = fmaf(a4.z, w3s[(k + 2) * 32 + lane], acc);
        acc = fmaf(a4.w, w3s[(k + 3) * 32 + lane], acc);
    }
    g_W23[(row0 + wid) * 32 + lane] = acc;

    if (blockIdx.x == 0 && wid == 0) {
        float bacc = (lane < L_) ? b3[lane] : 0.f;
#pragma unroll 8
        for (int k = 0; k < 512; k++)
            bacc = fmaf(b2s[k], w3s[k * 32 + lane], bacc);
        g_b23[lane] = bacc;
    }
}

// ======================= stage 2: Wc = W1 @ W23 (+bc) =======================
// grid 96 x 512thr: 16 rows/CTA, warp = 1 row
__global__ __launch_bounds__(512) void k_wc(const float* __restrict__ W1,
                                            const float* __restrict__ b1) {
    extern __shared__ float s[];
    float* w23s = s;                  // [1024*32]
    float* w1s  = s + FH_ * 32;       // [16*1024]
    float* b1s  = w1s + 16 * FH_;     // [1024]
    const int tid = threadIdx.x;

    {
        float4* d = (float4*)w23s;
        const float4* g = (const float4*)g_W23;
        for (int idx = tid; idx < FH_ * 32 / 4; idx += 512) d[idx] = g[idx];
    }
    const int row0 = blockIdx.x * 16;
    {
        float4* d = (float4*)w1s;
        const float4* g = (const float4*)(W1 + (size_t)row0 * FH_);
        for (int idx = tid; idx < 16 * FH_ / 4; idx += 512) d[idx] = g[idx];
    }
    if (tid < 256) ((float4*)b1s)[tid] = ((const float4*)b1)[tid];
    __syncthreads();

    const int wid = tid >> 5, lane = tid & 31;
    const float* arow = w1s + wid * FH_;
    float acc = 0.f;
#pragma unroll 4
    for (int k = 0; k < FH_; k += 4) {
        float4 a4 = *(const float4*)&arow[k];
        acc = fmaf(a4.x, w23s[(k + 0) * 32 + lane], acc);
        acc = fmaf(a4.y, w23s[(k + 1) * 32 + lane], acc);
        acc = fmaf(a4.z, w23s[(k + 2) * 32 + lane], acc);
        acc = fmaf(a4.w, w23s[(k + 3) * 32 + lane], acc);
    }
    g_Wc[(row0 + wid) * 32 + lane] = acc;

    if (blockIdx.x == 0 && wid == 0) {
        float bacc = g_b23[lane];
#pragma unroll 8
        for (int k = 0; k < FH_; k++)
            bacc = fmaf(b1s[k], w23s[k * 32 + lane], bacc);
        g_bc[lane] = bacc;
    }
}

// ======================= stage 3: pq = pooler @ Wc_bot + bc =======================
// grid 8 x 256thr: 8 rows/CTA, warp = 1 row
__global__ __launch_bounds__(256) void k_pq(const float* __restrict__ pooler) {
    extern __shared__ float s[];
    float* wcb = s;                   // [768*32]
    float* ps  = s + H_ * 32;         // [8*768]
    const int tid = threadIdx.x;

    {
        float4* d = (float4*)wcb;
        const float4* g = (const float4*)(g_Wc + H_ * 32);
        for (int idx = tid; idx < H_ * 32 / 4; idx += 256) d[idx] = g[idx];
    }
    const int b0 = blockIdx.x * 8;
    {
        float4* d = (float4*)ps;
        const float4* g = (const float4*)(pooler + (size_t)b0 * H_);
        for (int idx = tid; idx < 8 * H_ / 4; idx += 256) d[idx] = g[idx];
    }
    __syncthreads();

    const int wid = tid >> 5, lane = tid & 31;
    const float* prow = ps + wid * H_;
    float acc = g_bc[lane];
#pragma unroll 4
    for (int k = 0; k < H_; k += 4) {
        float4 a4 = *(const float4*)&prow[k];
        acc = fmaf(a4.x, wcb[(k + 0) * 32 + lane], acc);
        acc = fmaf(a4.y, wcb[(k + 1) * 32 + lane], acc);
        acc = fmaf(a4.z, wcb[(k + 2) * 32 + lane], acc);
        acc = fmaf(a4.w, wcb[(k + 3) * 32 + lane], acc);
    }
    g_pq[(b0 + wid) * 32 + lane] = acc;
}

// ======================= stage 4: fused gather + logits + loss =======================
// grid 128 x 512thr: 16 rows/CTA, warp = 1 row
__global__ __launch_bounds__(512) void k_main(const float* __restrict__ te,
                                              const int* __restrict__ pos,
                                              const float* __restrict__ labels) {
    extern __shared__ float s[];
    float* wct = s;                   // [768*32]
    float* as  = s + H_ * 32;         // [16*768]
    __shared__ float sml[16][5];
    const int tid = threadIdx.x;
    const int wid = tid >> 5, lane = tid & 31;

    {
        float4* d = (float4*)wct;
        const float4* g = (const float4*)g_Wc;
        for (int idx = tid; idx < H_ * 32 / 4; idx += 512) d[idx] = g[idx];
    }
    const int r0 = blockIdx.x * 16;
    {
        int gr = r0 + wid;     // 32 threads per row
        const float4* src = (const float4*)(te + ((size_t)(gr >> 5) * S_ + pos[gr]) * H_);
        float4* dst = (float4*)(as + wid * H_);
#pragma unroll
        for (int j = 0; j < 6; j++)
            dst[lane + j * 32] = src[lane + j * 32];
    }
    __syncthreads();

    const int gr = r0 + wid;
    const float* arow = as + wid * H_;
    float acc = 0.f;
#pragma unroll 8
    for (int k = 0; k < H_; k += 4) {
        float4 a4 = *(const float4*)&arow[k];
        acc = fmaf(a4.x, wct[(k + 0) * 32 + lane], acc);
        acc = fmaf(a4.y, wct[(k + 1) * 32 + lane], acc);
        acc = fmaf(a4.z, wct[(k + 2) * 32 + lane], acc);
        acc = fmaf(a4.w, wct[(k + 3) * 32 + lane], acc);
    }

    const bool active = (lane < L_);
    float x = acc + g_pq[(gr >> 5) * 32 + lane];
    float y = active ? labels[(size_t)gr * L_ + lane] : -1.0f;

    unsigned ball_bin  = __ballot_sync(0xffffffffu, active && (x > 0.f));
    unsigned ball_one  = __ballot_sync(0xffffffffu, active && (y > 0.5f));
    unsigned ball_real = __ballot_sync(0xffffffffu, active && (y != -1.0f));

    float sp  = fmaxf(x, 0.f) + log1pf(expf(-fabsf(x)));
    float bce = active ? (sp - x * y) : 0.f;
#pragma unroll
    for (int o = 16; o; o >>= 1) bce += __shfl_xor_sync(0xffffffffu, bce, o);

    if (lane == 0) {
        float mf = (ball_real != 0u) ? 1.f : 0.f;
        int co = __popc(ball_bin);
        int cl = __popc(ball_one);
        float cd = (float)(co - cl);
        bool eq = (mf != 0.f) && (co == 1) && (cl == 1);
        float pd = eq ? (float)(__ffs(ball_bin) - __ffs(ball_one)) : 0.f;
        sml[wid][0] = mf * bce;
        sml[wid][1] = mf;
        sml[wid][2] = mf * cd * cd;
        sml[wid][3] = pd * pd;
        sml[wid][4] = eq ? 1.f : 0.f;
    }
    __syncthreads();
    if (tid < 5) {
        float ssum = 0.f;
        for (int w = 0; w < 16; w++) ssum += sml[w][tid];   // fixed order
        g_part[blockIdx.x * 5 + tid] = ssum;
    }
}

// ======================= final reduce =======================
__global__ __launch_bounds__(128)
void k_final(float* __restrict__ out, int out_size)
{
    __shared__ float smf[128][5];
    int t = threadIdx.x;
    for (int c = 0; c < 5; c++) smf[t][c] = g_part[t * 5 + c];
    __syncthreads();
    for (int s = 64; s > 0; s >>= 1) {
        if (t < s)
            for (int c = 0; c < 5; c++) smf[t][c] += smf[t + s][c];
        __syncthreads();
    }
    if (t == 0) {
        float bce_loss   = smf[0][0] / (smf[0][1] * (float)L_);
        float count_loss = smf[0][2] / (float)MROWS;
        float pos_loss   = (smf[0][4] > 0.f) ? (smf[0][3] / smf[0][4]) : 0.f;
        float loss = bce_loss + 10.f * count_loss + 5.f * pos_loss;
        for (int i = 0; i < out_size; i++) out[i] = loss;
    }
}

// ======================= launch =======================
extern "C" void kernel_launch(void* const* d_in, const int* in_sizes, int n_in,
                              void* d_out, int out_size)
{
    const float* te   = (const float*)d_in[0];
    const float* pool = (const float*)d_in[1];
    const int*   pos  = (const int*)  d_in[2];
    const float* lab  = (const float*)d_in[3];
    const float* W1   = (const float*)d_in[4];
    const float* b1   = (const float*)d_in[5];
    const float* W2   = (const float*)d_in[6];
    const float* b2   = (const float*)d_in[7];
    const float* W3   = (const float*)d_in[8];
    const float* b3   = (const float*)d_in[9];

    const int SM_W23  = (512 * 32 + 16 * 512 + 512) * 4;        // 100,352
    const int SM_WC   = (FH_ * 32 + 16 * FH_ + FH_) * 4;        // 200,704
    const int SM_PQ   = (H_ * 32 + 8 * H_) * 4;                 // 122,880
    const int SM_MAIN = (H_ * 32 + 16 * H_) * 4;                // 147,456

    cudaFuncSetAttribute(k_w23,  cudaFuncAttributeMaxDynamicSharedMemorySize, SM_W23);
    cudaFuncSetAttribute(k_wc,   cudaFuncAttributeMaxDynamicSharedMemorySize, SM_WC);
    cudaFuncSetAttribute(k_pq,   cudaFuncAttributeMaxDynamicSharedMemorySize, SM_PQ);
    cudaFuncSetAttribute(k_main, cudaFuncAttributeMaxDynamicSharedMemorySize, SM_MAIN);

    k_w23<<<FH_ / 16, 512, SM_W23>>>(W2, W3, b2, b3);      // W23, b23
    k_wc<<<(2 * H_) / 16, 512, SM_WC>>>(W1, b1);           // Wc, bc
    k_pq<<<B_ / 8, 256, SM_PQ>>>(pool);                    // pq
    k_main<<<MROWS / 16, 512, SM_MAIN>>>(te, pos, lab);    // fused logits + loss
    k_final<<<1, 128>>>((float*)d_out, out_size);
}

// round 10
// speedup vs baseline: 1.2526x; 1.1537x over previous
#include <cuda_runtime.h>
#include <math.h>
#include <stdint.h>

#define B_   64
#define S_   512
#define P_   32
#define L_   30
#define H_   768
#define FH_  1024
#define MROWS (B_*P_)   // 2048

// ======================= device scratch (no allocation) =======================
__device__ float g_W23[FH_ * 32];      // W2@W3, padded cols  [1024][32]
__device__ float g_Wc[2 * H_ * 32];    // W1@W23              [1536][32]
__device__ float g_b23[32];            // b2@W3 + b3
__device__ float g_bc[32];             // b1@W23 + b23
__device__ float g_pq[B_ * 32];        // pooler@Wc_bot + bc  [64][32]
__device__ float g_part[64 * 5];

__device__ __forceinline__ uint32_t smem_u32(const void* p) {
    uint32_t a;
    asm("{ .reg .u64 t; cvta.to.shared.u64 t, %1; cvt.u32.u64 %0, t; }"
        : "=r"(a) : "l"(p));
    return a;
}
#define CP16(dst_u32, src_ptr) \
    asm volatile("cp.async.cg.shared.global [%0], [%1], 16;" \
        :: "r"(dst_u32), "l"(src_ptr))
#define CP_COMMIT() asm volatile("cp.async.commit_group;")
#define CP_WAIT0()  asm volatile("cp.async.wait_group 0;")

// ======================= stage 1: W23 = W2 @ W3 (+b23) =======================
// grid 32, 256thr: 8 warps x 4 rows = 32 rows/CTA
__global__ __launch_bounds__(256) void k_w23(const float* __restrict__ W2,
                                             const float* __restrict__ W3,
                                             const float* __restrict__ b2,
                                             const float* __restrict__ b3) {
    extern __shared__ float s[];
    float* w3s = s;                  // [512*32] 64KB
    float* w2s = s + 512 * 32;       // [32*512] 64KB
    const int tid = threadIdx.x;
    const int row0 = blockIdx.x * 32;

    for (int idx = tid; idx < 512 * 32; idx += 256) {
        int k2 = idx >> 5, l = idx & 31;
        w3s[idx] = (l < L_) ? W3[k2 * L_ + l] : 0.f;
    }
    {
        const uint32_t sa = smem_u32(w2s);
        const float* g = W2 + (size_t)row0 * 512;
#pragma unroll
        for (int j = 0; j < 16; j++) {           // 4096 cp16 chunks (32*512 floats)
            int c = tid + j * 256;
            CP16(sa + (uint32_t)c * 16, g + c * 4);
        }
        CP_COMMIT(); CP_WAIT0();
    }
    __syncthreads();

    const int wid = tid >> 5, lane = tid & 31;
    const float* a0 = w2s + (wid * 4 + 0) * 512;
    const float* a1 = w2s + (wid * 4 + 1) * 512;
    const float* a2 = w2s + (wid * 4 + 2) * 512;
    const float* a3 = w2s + (wid * 4 + 3) * 512;
    float acc[4] = {0.f, 0.f, 0.f, 0.f};
#pragma unroll 8
    for (int k = 0; k < 512; k += 4) {
        float4 v0 = *(const float4*)&a0[k];
        float4 v1 = *(const float4*)&a1[k];
        float4 v2 = *(const float4*)&a2[k];
        float4 v3 = *(const float4*)&a3[k];
        float w0 = w3s[(k + 0) * 32 + lane];
        float w1 = w3s[(k + 1) * 32 + lane];
        float w2v = w3s[(k + 2) * 32 + lane];
        float w3v = w3s[(k + 3) * 32 + lane];
        acc[0] = fmaf(v0.x, w0, acc[0]); acc[0] = fmaf(v0.y, w1, acc[0]);
        acc[0] = fmaf(v0.z, w2v, acc[0]); acc[0] = fmaf(v0.w, w3v, acc[0]);
        acc[1] = fmaf(v1.x, w0, acc[1]); acc[1] = fmaf(v1.y, w1, acc[1]);
        acc[1] = fmaf(v1.z, w2v, acc[1]); acc[1] = fmaf(v1.w, w3v, acc[1]);
        acc[2] = fmaf(v2.x, w0, acc[2]); acc[2] = fmaf(v2.y, w1, acc[2]);
        acc[2] = fmaf(v2.z, w2v, acc[2]); acc[2] = fmaf(v2.w, w3v, acc[2]);
        acc[3] = fmaf(v3.x, w0, acc[3]); acc[3] = fmaf(v3.y, w1, acc[3]);
        acc[3] = fmaf(v3.z, w2v, acc[3]); acc[3] = fmaf(v3.w, w3v, acc[3]);
    }
#pragma unroll
    for (int r = 0; r < 4; r++)
        g_W23[(row0 + wid * 4 + r) * 32 + lane] = acc[r];

    if (blockIdx.x == 0 && wid == 0) {
        float bacc = (lane < L_) ? b3[lane] : 0.f;
#pragma unroll 8
        for (int k = 0; k < 512; k++)
            bacc = fmaf(b2[k], w3s[k * 32 + lane], bacc);
        g_b23[lane] = bacc;
    }
}

// ======================= stage 2: Wc = W1 @ W23 (+bc) =======================
// grid 96, 128thr: 4 warps x 4 rows = 16 rows/CTA
__global__ __launch_bounds__(128) void k_wc(const float* __restrict__ W1,
                                            const float* __restrict__ b1) {
    extern __shared__ float s[];
    float* w23s = s;                  // [1024*32] 128KB
    float* w1s  = s + FH_ * 32;       // [16*1024]  64KB
    const int tid = threadIdx.x;
    const int row0 = blockIdx.x * 16;

    {
        const uint32_t sa = smem_u32(w23s);
        const float* g = g_W23;
#pragma unroll
        for (int j = 0; j < 64; j++) {           // 8192 cp16
            int c = tid + j * 128;
            CP16(sa + (uint32_t)c * 16, g + c * 4);
        }
        const uint32_t sb = smem_u32(w1s);
        const float* g1 = W1 + (size_t)row0 * FH_;
#pragma unroll
        for (int j = 0; j < 32; j++) {           // 4096 cp16
            int c = tid + j * 128;
            CP16(sb + (uint32_t)c * 16, g1 + c * 4);
        }
        CP_COMMIT(); CP_WAIT0();
    }
    __syncthreads();

    const int wid = tid >> 5, lane = tid & 31;
    const float* a0 = w1s + (wid * 4 + 0) * FH_;
    const float* a1 = w1s + (wid * 4 + 1) * FH_;
    const float* a2 = w1s + (wid * 4 + 2) * FH_;
    const float* a3 = w1s + (wid * 4 + 3) * FH_;
    float acc[4] = {0.f, 0.f, 0.f, 0.f};
#pragma unroll 8
    for (int k = 0; k < FH_; k += 4) {
        float4 v0 = *(const float4*)&a0[k];
        float4 v1 = *(const float4*)&a1[k];
        float4 v2 = *(const float4*)&a2[k];
        float4 v3 = *(const float4*)&a3[k];
        float w0 = w23s[(k + 0) * 32 + lane];
        float w1v = w23s[(k + 1) * 32 + lane];
        float w2v = w23s[(k + 2) * 32 + lane];
        float w3v = w23s[(k + 3) * 32 + lane];
        acc[0] = fmaf(v0.x, w0, acc[0]); acc[0] = fmaf(v0.y, w1v, acc[0]);
        acc[0] = fmaf(v0.z, w2v, acc[0]); acc[0] = fmaf(v0.w, w3v, acc[0]);
        acc[1] = fmaf(v1.x, w0, acc[1]); acc[1] = fmaf(v1.y, w1v, acc[1]);
        acc[1] = fmaf(v1.z, w2v, acc[1]); acc[1] = fmaf(v1.w, w3v, acc[1]);
        acc[2] = fmaf(v2.x, w0, acc[2]); acc[2] = fmaf(v2.y, w1v, acc[2]);
        acc[2] = fmaf(v2.z, w2v, acc[2]); acc[2] = fmaf(v2.w, w3v, acc[2]);
        acc[3] = fmaf(v3.x, w0, acc[3]); acc[3] = fmaf(v3.y, w1v, acc[3]);
        acc[3] = fmaf(v3.z, w2v, acc[3]); acc[3] = fmaf(v3.w, w3v, acc[3]);
    }
#pragma unroll
    for (int r = 0; r < 4; r++)
        g_Wc[(row0 + wid * 4 + r) * 32 + lane] = acc[r];

    if (blockIdx.x == 0 && wid == 0) {
        float bacc = g_b23[lane];
#pragma unroll 8
        for (int k = 0; k < FH_; k++)
            bacc = fmaf(b1[k], w23s[k * 32 + lane], bacc);
        g_bc[lane] = bacc;
    }
}

// ======================= stage 3: pq = pooler @ Wc_bot + bc =======================
// grid 64, 32thr: one warp per batch row, Wc_bot streamed from global (L2)
__global__ __launch_bounds__(32) void k_pq(const float* __restrict__ pooler) {
    const int lane = threadIdx.x;
    const int row = blockIdx.x;
    const float* prow = pooler + (size_t)row * H_;
    const float* wcb = g_Wc + H_ * 32;
    float acc = g_bc[lane];
#pragma unroll 8
    for (int k = 0; k < H_; k += 4) {
        float4 a4 = *(const float4*)&prow[k];     // uniform LDG.128
        acc = fmaf(a4.x, wcb[(k + 0) * 32 + lane], acc);
        acc = fmaf(a4.y, wcb[(k + 1) * 32 + lane], acc);
        acc = fmaf(a4.z, wcb[(k + 2) * 32 + lane], acc);
        acc = fmaf(a4.w, wcb[(k + 3) * 32 + lane], acc);
    }
    g_pq[row * 32 + lane] = acc;
}

// ======================= stage 4: fused gather + logits + loss =======================
// grid 64, 256thr: 8 warps x 4 rows = 32 rows/CTA (= one batch exactly)
__global__ __launch_bounds__(256) void k_main(const float* __restrict__ te,
                                              const int* __restrict__ pos,
                                              const float* __restrict__ labels) {
    extern __shared__ float s[];
    float* wct = s;                   // [768*32]  96KB
    float* as  = s + H_ * 32;         // [32*768]  96KB
    __shared__ float sml[8][5];
    const int tid = threadIdx.x;
    const int wid = tid >> 5, lane = tid & 31;
    const int r0 = blockIdx.x * 32;
    const int batch = r0 >> 5;

    {
        const uint32_t sa = smem_u32(wct);
        const float* g = g_Wc;
#pragma unroll
        for (int j = 0; j < 24; j++) {           // 6144 cp16
            int c = tid + j * 256;
            CP16(sa + (uint32_t)c * 16, g + c * 4);
        }
        const uint32_t sb = smem_u32(as);
#pragma unroll
        for (int j = 0; j < 24; j++) {           // 6144 cp16 (192 per row)
            int c = tid + j * 256;
            int row = c / 192, ch = c % 192;
            const float* src = te + ((size_t)batch * S_ + pos[r0 + row]) * H_ + ch * 4;
            CP16(sb + (uint32_t)(row * H_ + ch * 4) * 4, src);
        }
        CP_COMMIT(); CP_WAIT0();
    }
    __syncthreads();

    const float* a0 = as + (wid * 4 + 0) * H_;
    const float* a1 = as + (wid * 4 + 1) * H_;
    const float* a2 = as + (wid * 4 + 2) * H_;
    const float* a3 = as + (wid * 4 + 3) * H_;
    float acc[4] = {0.f, 0.f, 0.f, 0.f};
#pragma unroll 8
    for (int k = 0; k < H_; k += 4) {
        float4 v0 = *(const float4*)&a0[k];
        float4 v1 = *(const float4*)&a1[k];
        float4 v2 = *(const float4*)&a2[k];
        float4 v3 = *(const float4*)&a3[k];
        float w0 = wct[(k + 0) * 32 + lane];
        float w1 = wct[(k + 1) * 32 + lane];
        float w2 = wct[(k + 2) * 32 + lane];
        float w3 = wct[(k + 3) * 32 + lane];
        acc[0] = fmaf(v0.x, w0, acc[0]); acc[0] = fmaf(v0.y, w1, acc[0]);
        acc[0] = fmaf(v0.z, w2, acc[0]); acc[0] = fmaf(v0.w, w3, acc[0]);
        acc[1] = fmaf(v1.x, w0, acc[1]); acc[1] = fmaf(v1.y, w1, acc[1]);
        acc[1] = fmaf(v1.z, w2, acc[1]); acc[1] = fmaf(v1.w, w3, acc[1]);
        acc[2] = fmaf(v2.x, w0, acc[2]); acc[2] = fmaf(v2.y, w1, acc[2]);
        acc[2] = fmaf(v2.z, w2, acc[2]); acc[2] = fmaf(v2.w, w3, acc[2]);
        acc[3] = fmaf(v3.x, w0, acc[3]); acc[3] = fmaf(v3.y, w1, acc[3]);
        acc[3] = fmaf(v3.z, w2, acc[3]); acc[3] = fmaf(v3.w, w3, acc[3]);
    }

    const bool active = (lane < L_);
    const float pqv = g_pq[batch * 32 + lane];
    float st0 = 0.f, st1 = 0.f, st2 = 0.f, st3 = 0.f, st4 = 0.f;
#pragma unroll
    for (int r = 0; r < 4; r++) {
        int gr = r0 + wid * 4 + r;
        float x = acc[r] + pqv;
        float y = active ? labels[(size_t)gr * L_ + lane] : -1.0f;

        unsigned ball_bin  = __ballot_sync(0xffffffffu, active && (x > 0.f));
        unsigned ball_one  = __ballot_sync(0xffffffffu, active && (y > 0.5f));
        unsigned ball_real = __ballot_sync(0xffffffffu, active && (y != -1.0f));

        float sp  = fmaxf(x, 0.f) + log1pf(expf(-fabsf(x)));
        float bce = active ? (sp - x * y) : 0.f;
#pragma unroll
        for (int o = 16; o; o >>= 1) bce += __shfl_xor_sync(0xffffffffu, bce, o);

        if (lane == 0) {
            float mf = (ball_real != 0u) ? 1.f : 0.f;
            int co = __popc(ball_bin);
            int cl = __popc(ball_one);
            float cd = (float)(co - cl);
            bool eq = (mf != 0.f) && (co == 1) && (cl == 1);
            float pd = eq ? (float)(__ffs(ball_bin) - __ffs(ball_one)) : 0.f;
            st0 += mf * bce;
            st1 += mf;
            st2 += mf * cd * cd;
            st3 += pd * pd;
            st4 += eq ? 1.f : 0.f;
        }
    }
    if (lane == 0) {
        sml[wid][0] = st0; sml[wid][1] = st1; sml[wid][2] = st2;
        sml[wid][3] = st3; sml[wid][4] = st4;
    }
    __syncthreads();
    if (tid < 5) {
        float ssum = 0.f;
        for (int w = 0; w < 8; w++) ssum += sml[w][tid];   // fixed order
        g_part[blockIdx.x * 5 + tid] = ssum;
    }
}

// ======================= final reduce =======================
__global__ __launch_bounds__(64)
void k_final(float* __restrict__ out, int out_size)
{
    __shared__ float smf[64][5];
    int t = threadIdx.x;
    for (int c = 0; c < 5; c++) smf[t][c] = g_part[t * 5 + c];
    __syncthreads();
    for (int s = 32; s > 0; s >>= 1) {
        if (t < s)
            for (int c = 0; c < 5; c++) smf[t][c] += smf[t + s][c];
        __syncthreads();
    }
    if (t == 0) {
        float bce_loss   = smf[0][0] / (smf[0][1] * (float)L_);
        float count_loss = smf[0][2] / (float)MROWS;
        float pos_loss   = (smf[0][4] > 0.f) ? (smf[0][3] / smf[0][4]) : 0.f;
        float loss = bce_loss + 10.f * count_loss + 5.f * pos_loss;
        for (int i = 0; i < out_size; i++) out[i] = loss;
    }
}

// ======================= launch =======================
extern "C" void kernel_launch(void* const* d_in, const int* in_sizes, int n_in,
                              void* d_out, int out_size)
{
    const float* te   = (const float*)d_in[0];
    const float* pool = (const float*)d_in[1];
    const int*   pos  = (const int*)  d_in[2];
    const float* lab  = (const float*)d_in[3];
    const float* W1   = (const float*)d_in[4];
    const float* b1   = (const float*)d_in[5];
    const float* W2   = (const float*)d_in[6];
    const float* b2   = (const float*)d_in[7];
    const float* W3   = (const float*)d_in[8];
    const float* b3   = (const float*)d_in[9];

    const int SM_W23  = (512 * 32 + 32 * 512) * 4;     // 131072
    const int SM_WC   = (FH_ * 32 + 16 * FH_) * 4;     // 196608
    const int SM_MAIN = (H_ * 32 + 32 * H_) * 4;       // 196608

    cudaFuncSetAttribute(k_w23,  cudaFuncAttributeMaxDynamicSharedMemorySize, SM_W23);
    cudaFuncSetAttribute(k_wc,   cudaFuncAttributeMaxDynamicSharedMemorySize, SM_WC);
    cudaFuncSetAttribute(k_main, cudaFuncAttributeMaxDynamicSharedMemorySize, SM_MAIN);

    k_w23<<<FH_ / 32, 256, SM_W23>>>(W2, W3, b2, b3);   // W23, b23
    k_wc<<<(2 * H_) / 16, 128, SM_WC>>>(W1, b1);        // Wc, bc
    k_pq<<<B_, 32>>>(pool);                             // pq
    k_main<<<MROWS / 32, 256, SM_MAIN>>>(te, pos, lab); // fused logits + loss
    k_final<<<1, 64>>>((float*)d_out, out_size);
}

// round 11
// speedup vs baseline: 1.4333x; 1.1443x over previous
#include <cuda_runtime.h>
#include <math.h>
#include <stdint.h>

#define B_   64
#define S_   512
#define P_   32
#define L_   30
#define H_   768
#define FH_  1024
#define MROWS (B_*P_)   // 2048

// ======================= device scratch (no allocation) =======================
__device__ float g_W23[FH_ * 32];      // W2@W3, padded cols  [1024][32]
__device__ float g_Wc[2 * H_ * 32];    // W1@W23              [1536][32]
__device__ float g_b23[32];            // b2@W3 + b3
__device__ float g_bc[32];             // b1@W23 + b23
__device__ float g_part[128 * 5];
__device__ unsigned g_done;

__device__ __forceinline__ uint32_t smem_u32(const void* p) {
    uint32_t a;
    asm("{ .reg .u64 t; cvta.to.shared.u64 t, %1; cvt.u32.u64 %0, t; }"
        : "=r"(a) : "l"(p));
    return a;
}
#define CP16(dst_u32, src_ptr) \
    asm volatile("cp.async.cg.shared.global [%0], [%1], 16;" \
        :: "r"(dst_u32), "l"(src_ptr))
#define CP_COMMIT() asm volatile("cp.async.commit_group;")
#define CP_WAIT0()  asm volatile("cp.async.wait_group 0;")

// ======================= stage 1: W23 = W2 @ W3 (+b23) =======================
// grid 32, 256thr: 8 warps x 4 rows = 32 rows/CTA
__global__ __launch_bounds__(256) void k_w23(const float* __restrict__ W2,
                                             const float* __restrict__ W3,
                                             const float* __restrict__ b2,
                                             const float* __restrict__ b3) {
    extern __shared__ float s[];
    float* w3s = s;                  // [512*32] 64KB
    float* w2s = s + 512 * 32;       // [32*512] 64KB
    const int tid = threadIdx.x;
    const int row0 = blockIdx.x * 32;

    if (blockIdx.x == 0 && tid == 0) g_done = 0;   // reset final-reduce counter

    for (int idx = tid; idx < 512 * 32; idx += 256) {
        int k2 = idx >> 5, l = idx & 31;
        w3s[idx] = (l < L_) ? W3[k2 * L_ + l] : 0.f;
    }
    {
        const uint32_t sa = smem_u32(w2s);
        const float* g = W2 + (size_t)row0 * 512;
#pragma unroll
        for (int j = 0; j < 16; j++) {           // 4096 cp16 chunks
            int c = tid + j * 256;
            CP16(sa + (uint32_t)c * 16, g + c * 4);
        }
        CP_COMMIT(); CP_WAIT0();
    }
    __syncthreads();

    const int wid = tid >> 5, lane = tid & 31;
    const float* a0 = w2s + (wid * 4 + 0) * 512;
    const float* a1 = w2s + (wid * 4 + 1) * 512;
    const float* a2 = w2s + (wid * 4 + 2) * 512;
    const float* a3 = w2s + (wid * 4 + 3) * 512;
    float acc[4] = {0.f, 0.f, 0.f, 0.f};
#pragma unroll 8
    for (int k = 0; k < 512; k += 4) {
        float4 v0 = *(const float4*)&a0[k];
        float4 v1 = *(const float4*)&a1[k];
        float4 v2 = *(const float4*)&a2[k];
        float4 v3 = *(const float4*)&a3[k];
        float w0 = w3s[(k + 0) * 32 + lane];
        float w1 = w3s[(k + 1) * 32 + lane];
        float w2v = w3s[(k + 2) * 32 + lane];
        float w3v = w3s[(k + 3) * 32 + lane];
        acc[0] = fmaf(v0.x, w0, acc[0]); acc[0] = fmaf(v0.y, w1, acc[0]);
        acc[0] = fmaf(v0.z, w2v, acc[0]); acc[0] = fmaf(v0.w, w3v, acc[0]);
        acc[1] = fmaf(v1.x, w0, acc[1]); acc[1] = fmaf(v1.y, w1, acc[1]);
        acc[1] = fmaf(v1.z, w2v, acc[1]); acc[1] = fmaf(v1.w, w3v, acc[1]);
        acc[2] = fmaf(v2.x, w0, acc[2]); acc[2] = fmaf(v2.y, w1, acc[2]);
        acc[2] = fmaf(v2.z, w2v, acc[2]); acc[2] = fmaf(v2.w, w3v, acc[2]);
        acc[3] = fmaf(v3.x, w0, acc[3]); acc[3] = fmaf(v3.y, w1, acc[3]);
        acc[3] = fmaf(v3.z, w2v, acc[3]); acc[3] = fmaf(v3.w, w3v, acc[3]);
    }
#pragma unroll
    for (int r = 0; r < 4; r++)
        g_W23[(row0 + wid * 4 + r) * 32 + lane] = acc[r];

    if (blockIdx.x == 0 && wid == 0) {
        float bacc = (lane < L_) ? b3[lane] : 0.f;
#pragma unroll 8
        for (int k = 0; k < 512; k++)
            bacc = fmaf(b2[k], w3s[k * 32 + lane], bacc);
        g_b23[lane] = bacc;
    }
}

// ======================= stage 2: Wc = W1 @ W23 (+bc) =======================
// grid 96, 128thr: 4 warps x 4 rows = 16 rows/CTA
__global__ __launch_bounds__(128) void k_wc(const float* __restrict__ W1,
                                            const float* __restrict__ b1) {
    extern __shared__ float s[];
    float* w23s = s;                  // [1024*32] 128KB
    float* w1s  = s + FH_ * 32;       // [16*1024]  64KB
    const int tid = threadIdx.x;
    const int row0 = blockIdx.x * 16;

    {
        const uint32_t sa = smem_u32(w23s);
        const float* g = g_W23;
#pragma unroll
        for (int j = 0; j < 64; j++) {           // 8192 cp16
            int c = tid + j * 128;
            CP16(sa + (uint32_t)c * 16, g + c * 4);
        }
        const uint32_t sb = smem_u32(w1s);
        const float* g1 = W1 + (size_t)row0 * FH_;
#pragma unroll
        for (int j = 0; j < 32; j++) {           // 4096 cp16
            int c = tid + j * 128;
            CP16(sb + (uint32_t)c * 16, g1 + c * 4);
        }
        CP_COMMIT(); CP_WAIT0();
    }
    __syncthreads();

    const int wid = tid >> 5, lane = tid & 31;
    const float* a0 = w1s + (wid * 4 + 0) * FH_;
    const float* a1 = w1s + (wid * 4 + 1) * FH_;
    const float* a2 = w1s + (wid * 4 + 2) * FH_;
    const float* a3 = w1s + (wid * 4 + 3) * FH_;
    float acc[4] = {0.f, 0.f, 0.f, 0.f};
#pragma unroll 8
    for (int k = 0; k < FH_; k += 4) {
        float4 v0 = *(const float4*)&a0[k];
        float4 v1 = *(const float4*)&a1[k];
        float4 v2 = *(const float4*)&a2[k];
        float4 v3 = *(const float4*)&a3[k];
        float w0 = w23s[(k + 0) * 32 + lane];
        float w1v = w23s[(k + 1) * 32 + lane];
        float w2v = w23s[(k + 2) * 32 + lane];
        float w3v = w23s[(k + 3) * 32 + lane];
        acc[0] = fmaf(v0.x, w0, acc[0]); acc[0] = fmaf(v0.y, w1v, acc[0]);
        acc[0] = fmaf(v0.z, w2v, acc[0]); acc[0] = fmaf(v0.w, w3v, acc[0]);
        acc[1] = fmaf(v1.x, w0, acc[1]); acc[1] = fmaf(v1.y, w1v, acc[1]);
        acc[1] = fmaf(v1.z, w2v, acc[1]); acc[1] = fmaf(v1.w, w3v, acc[1]);
        acc[2] = fmaf(v2.x, w0, acc[2]); acc[2] = fmaf(v2.y, w1v, acc[2]);
        acc[2] = fmaf(v2.z, w2v, acc[2]); acc[2] = fmaf(v2.w, w3v, acc[2]);
        acc[3] = fmaf(v3.x, w0, acc[3]); acc[3] = fmaf(v3.y, w1v, acc[3]);
        acc[3] = fmaf(v3.z, w2v, acc[3]); acc[3] = fmaf(v3.w, w3v, acc[3]);
    }
#pragma unroll
    for (int r = 0; r < 4; r++)
        g_Wc[(row0 + wid * 4 + r) * 32 + lane] = acc[r];

    if (blockIdx.x == 0 && wid == 0) {
        float bacc = g_b23[lane];
#pragma unroll 8
        for (int k = 0; k < FH_; k++)
            bacc = fmaf(b1[k], w23s[k * 32 + lane], bacc);
        g_bc[lane] = bacc;
    }
}

// ======================= stage 3: fused gather + pq + logits + loss + final =======================
// grid 128, 128thr: 4 warps x 4 rows = 16 rows/CTA (half a batch)
__global__ __launch_bounds__(128) void k_main(const float* __restrict__ te,
                                              const int* __restrict__ pos,
                                              const float* __restrict__ labels,
                                              const float* __restrict__ pooler,
                                              float* __restrict__ out, int out_size) {
    extern __shared__ float s[];
    float* wct = s;                   // [768*32]  96KB
    float* as  = s + H_ * 32;         // [16*768]  48KB
    __shared__ float pqs[4][32];
    __shared__ float sml[4][5];
    __shared__ float red[128][5];
    __shared__ unsigned s_done;
    const int tid = threadIdx.x;
    const int wid = tid >> 5, lane = tid & 31;
    const int r0 = blockIdx.x * 16;
    const int batch = blockIdx.x >> 1;

    // issue staging (wct + 16 gathered A rows)
    {
        const uint32_t sa = smem_u32(wct);
        const float* g = g_Wc;
#pragma unroll
        for (int j = 0; j < 48; j++) {           // 6144 cp16
            int c = tid + j * 128;
            CP16(sa + (uint32_t)c * 16, g + c * 4);
        }
        const uint32_t sb = smem_u32(as);
#pragma unroll
        for (int j = 0; j < 24; j++) {           // 3072 cp16 (192 per row)
            int c = tid + j * 128;
            int row = c / 192, ch = c % 192;
            const float* src = te + ((size_t)batch * S_ + pos[r0 + row]) * H_ + ch * 4;
            CP16(sb + (uint32_t)(row * H_ + ch * 4) * 4, src);
        }
        CP_COMMIT();
    }

    // pq for this batch, overlapped with staging (reads global only)
    {
        const float* wcb = g_Wc + H_ * 32;
        const float* prow = pooler + (size_t)batch * H_;
        const int kb = wid * 192;
        float pacc = 0.f;
#pragma unroll 8
        for (int kk = 0; kk < 192; kk += 4) {
            float4 a4 = *(const float4*)&prow[kb + kk];
            pacc = fmaf(a4.x, wcb[(kb + kk + 0) * 32 + lane], pacc);
            pacc = fmaf(a4.y, wcb[(kb + kk + 1) * 32 + lane], pacc);
            pacc = fmaf(a4.z, wcb[(kb + kk + 2) * 32 + lane], pacc);
            pacc = fmaf(a4.w, wcb[(kb + kk + 3) * 32 + lane], pacc);
        }
        pqs[wid][lane] = pacc;
    }
    CP_WAIT0();
    __syncthreads();
    const float pqv = ((pqs[0][lane] + pqs[1][lane]) + (pqs[2][lane] + pqs[3][lane]))
                      + g_bc[lane];

    const float* a0 = as + (wid * 4 + 0) * H_;
    const float* a1 = as + (wid * 4 + 1) * H_;
    const float* a2 = as + (wid * 4 + 2) * H_;
    const float* a3 = as + (wid * 4 + 3) * H_;
    float acc[4] = {0.f, 0.f, 0.f, 0.f};
#pragma unroll 8
    for (int k = 0; k < H_; k += 4) {
        float4 v0 = *(const float4*)&a0[k];
        float4 v1 = *(const float4*)&a1[k];
        float4 v2 = *(const float4*)&a2[k];
        float4 v3 = *(const float4*)&a3[k];
        float w0 = wct[(k + 0) * 32 + lane];
        float w1 = wct[(k + 1) * 32 + lane];
        float w2 = wct[(k + 2) * 32 + lane];
        float w3 = wct[(k + 3) * 32 + lane];
        acc[0] = fmaf(v0.x, w0, acc[0]); acc[0] = fmaf(v0.y, w1, acc[0]);
        acc[0] = fmaf(v0.z, w2, acc[0]); acc[0] = fmaf(v0.w, w3, acc[0]);
        acc[1] = fmaf(v1.x, w0, acc[1]); acc[1] = fmaf(v1.y, w1, acc[1]);
        acc[1] = fmaf(v1.z, w2, acc[1]); acc[1] = fmaf(v1.w, w3, acc[1]);
        acc[2] = fmaf(v2.x, w0, acc[2]); acc[2] = fmaf(v2.y, w1, acc[2]);
        acc[2] = fmaf(v2.z, w2, acc[2]); acc[2] = fmaf(v2.w, w3, acc[2]);
        acc[3] = fmaf(v3.x, w0, acc[3]); acc[3] = fmaf(v3.y, w1, acc[3]);
        acc[3] = fmaf(v3.z, w2, acc[3]); acc[3] = fmaf(v3.w, w3, acc[3]);
    }

    const bool active = (lane < L_);
    float st0 = 0.f, st1 = 0.f, st2 = 0.f, st3 = 0.f, st4 = 0.f;
#pragma unroll
    for (int r = 0; r < 4; r++) {
        int gr = r0 + wid * 4 + r;
        float x = acc[r] + pqv;
        float y = active ? labels[(size_t)gr * L_ + lane] : -1.0f;

        unsigned ball_bin  = __ballot_sync(0xffffffffu, active && (x > 0.f));
        unsigned ball_one  = __ballot_sync(0xffffffffu, active && (y > 0.5f));
        unsigned ball_real = __ballot_sync(0xffffffffu, active && (y != -1.0f));

        float sp  = fmaxf(x, 0.f) + log1pf(expf(-fabsf(x)));
        float bce = active ? (sp - x * y) : 0.f;
#pragma unroll
        for (int o = 16; o; o >>= 1) bce += __shfl_xor_sync(0xffffffffu, bce, o);

        if (lane == 0) {
            float mf = (ball_real != 0u) ? 1.f : 0.f;
            int co = __popc(ball_bin);
            int cl = __popc(ball_one);
            float cd = (float)(co - cl);
            bool eq = (mf != 0.f) && (co == 1) && (cl == 1);
            float pd = eq ? (float)(__ffs(ball_bin) - __ffs(ball_one)) : 0.f;
            st0 += mf * bce;
            st1 += mf;
            st2 += mf * cd * cd;
            st3 += pd * pd;
            st4 += eq ? 1.f : 0.f;
        }
    }
    if (lane == 0) {
        sml[wid][0] = st0; sml[wid][1] = st1; sml[wid][2] = st2;
        sml[wid][3] = st3; sml[wid][4] = st4;
    }
    __syncthreads();
    if (tid < 5) {
        float ssum = 0.f;
        for (int w = 0; w < 4; w++) ssum += sml[w][tid];   // fixed order
        g_part[blockIdx.x * 5 + tid] = ssum;
    }

    // ---- last-block final reduction (deterministic: fixed-order sum) ----
    __threadfence();
    __syncthreads();
    if (tid == 0) s_done = atomicAdd(&g_done, 1u);
    __syncthreads();
    if (s_done == 127u) {
        __threadfence();
        for (int c = 0; c < 5; c++) red[tid][c] = g_part[tid * 5 + c];
        __syncthreads();
        for (int st = 64; st > 0; st >>= 1) {
            if (tid < st)
                for (int c = 0; c < 5; c++) red[tid][c] += red[tid + st][c];
            __syncthreads();
        }
        if (tid == 0) {
            float bce_loss   = red[0][0] / (red[0][1] * (float)L_);
            float count_loss = red[0][2] / (float)MROWS;
            float pos_loss   = (red[0][4] > 0.f) ? (red[0][3] / red[0][4]) : 0.f;
            float loss = bce_loss + 10.f * count_loss + 5.f * pos_loss;
            for (int i = 0; i < out_size; i++) out[i] = loss;
        }
    }
}

// ======================= launch =======================
extern "C" void kernel_launch(void* const* d_in, const int* in_sizes, int n_in,
                              void* d_out, int out_size)
{
    const float* te   = (const float*)d_in[0];
    const float* pool = (const float*)d_in[1];
    const int*   pos  = (const int*)  d_in[2];
    const float* lab  = (const float*)d_in[3];
    const float* W1   = (const float*)d_in[4];
    const float* b1   = (const float*)d_in[5];
    const float* W2   = (const float*)d_in[6];
    const float* b2   = (const float*)d_in[7];
    const float* W3   = (const float*)d_in[8];
    const float* b3   = (const float*)d_in[9];

    const int SM_W23  = (512 * 32 + 32 * 512) * 4;     // 131072
    const int SM_WC   = (FH_ * 32 + 16 * FH_) * 4;     // 196608
    const int SM_MAIN = (H_ * 32 + 16 * H_) * 4;       // 147456

    cudaFuncSetAttribute(k_w23,  cudaFuncAttributeMaxDynamicSharedMemorySize, SM_W23);
    cudaFuncSetAttribute(k_wc,   cudaFuncAttributeMaxDynamicSharedMemorySize, SM_WC);
    cudaFuncSetAttribute(k_main, cudaFuncAttributeMaxDynamicSharedMemorySize, SM_MAIN);

    k_w23<<<FH_ / 32, 256, SM_W23>>>(W2, W3, b2, b3);   // W23, b23 (+reset counter)
    k_wc<<<(2 * H_) / 16, 128, SM_WC>>>(W1, b1);        // Wc, bc
    k_main<<<MROWS / 16, 128, SM_MAIN>>>(te, pos, lab, pool,
                                         (float*)d_out, out_size);
}

// round 12
// speedup vs baseline: 2.2897x; 1.5974x over previous
#include <cuda_runtime.h>
#include <math.h>
#include <stdint.h>

#define B_   64
#define S_   512
#define P_   32
#define L_   30
#define H_   768
#define FH_  1024
#define MROWS (B_*P_)   // 2048

// ======================= device scratch (no allocation) =======================
__device__ float g_W23[FH_ * 32];      // W2@W3, padded cols  [1024][32]
__device__ float g_Wc[2 * H_ * 32];    // W1@W23              [1536][32]
__device__ float g_b23[32];            // b2@W3 + b3
__device__ float g_bc[32];             // b1@W23 + b23
__device__ float g_part[128 * 5];
__device__ unsigned g_done;

__device__ __forceinline__ uint32_t smem_u32(const void* p) {
    uint32_t a;
    asm("{ .reg .u64 t; cvta.to.shared.u64 t, %1; cvt.u32.u64 %0, t; }"
        : "=r"(a) : "l"(p));
    return a;
}
#define CP16(dst_u32, src_ptr) \
    asm volatile("cp.async.cg.shared.global [%0], [%1], 16;" \
        :: "r"(dst_u32), "l"(src_ptr))
#define CP_COMMIT() asm volatile("cp.async.commit_group;")
#define CP_WAIT0()  asm volatile("cp.async.wait_group 0;")

// ======================= stage 1: W23 = W2 @ W3 (+b23) =======================
// grid 64, 512thr: 16 warps x 1 row = 16 rows/CTA; 4-way k-partial ILP
__global__ __launch_bounds__(512) void k_w23(const float* __restrict__ W2,
                                             const float* __restrict__ W3,
                                             const float* __restrict__ b2,
                                             const float* __restrict__ b3) {
    extern __shared__ float s[];
    float* w3s = s;                  // [512*32] 64KB
    float* w2s = s + 512 * 32;       // [16*512] 32KB
    __shared__ float bpart[16][32];
    const int tid = threadIdx.x;
    const int wid = tid >> 5, lane = tid & 31;
    const int row0 = blockIdx.x * 16;

    if (blockIdx.x == 0 && tid == 0) g_done = 0;   // reset final-reduce counter

    // stage W3 -> padded [512][32]
    for (int idx = tid; idx < 512 * 32; idx += 512) {
        int k2 = idx >> 5, l = idx & 31;
        w3s[idx] = (l < L_) ? W3[k2 * L_ + l] : 0.f;
    }
    // stage 16 W2 rows (2048 cp16)
    {
        const uint32_t sa = smem_u32(w2s);
        const float* g = W2 + (size_t)row0 * 512;
#pragma unroll
        for (int j = 0; j < 4; j++) {
            int c = tid + j * 512;
            CP16(sa + (uint32_t)c * 16, g + c * 4);
        }
        CP_COMMIT(); CP_WAIT0();
    }
    __syncthreads();

    const float* a = w2s + wid * 512;
    float p0 = 0.f, p1 = 0.f, p2 = 0.f, p3 = 0.f;
#pragma unroll 4
    for (int k = 0; k < 512; k += 16) {
        float4 v0 = *(const float4*)&a[k];
        float4 v1 = *(const float4*)&a[k + 4];
        float4 v2 = *(const float4*)&a[k + 8];
        float4 v3 = *(const float4*)&a[k + 12];
        p0 = fmaf(v0.x, w3s[(k + 0) * 32 + lane], p0);
        p0 = fmaf(v0.y, w3s[(k + 1) * 32 + lane], p0);
        p0 = fmaf(v0.z, w3s[(k + 2) * 32 + lane], p0);
        p0 = fmaf(v0.w, w3s[(k + 3) * 32 + lane], p0);
        p1 = fmaf(v1.x, w3s[(k + 4) * 32 + lane], p1);
        p1 = fmaf(v1.y, w3s[(k + 5) * 32 + lane], p1);
        p1 = fmaf(v1.z, w3s[(k + 6) * 32 + lane], p1);
        p1 = fmaf(v1.w, w3s[(k + 7) * 32 + lane], p1);
        p2 = fmaf(v2.x, w3s[(k + 8) * 32 + lane], p2);
        p2 = fmaf(v2.y, w3s[(k + 9) * 32 + lane], p2);
        p2 = fmaf(v2.z, w3s[(k + 10) * 32 + lane], p2);
        p2 = fmaf(v2.w, w3s[(k + 11) * 32 + lane], p2);
        p3 = fmaf(v3.x, w3s[(k + 12) * 32 + lane], p3);
        p3 = fmaf(v3.y, w3s[(k + 13) * 32 + lane], p3);
        p3 = fmaf(v3.z, w3s[(k + 14) * 32 + lane], p3);
        p3 = fmaf(v3.w, w3s[(k + 15) * 32 + lane], p3);
    }
    g_W23[(row0 + wid) * 32 + lane] = (p0 + p1) + (p2 + p3);

    // b23 on CTA 0: 16 warps x 32-k partials, fixed-order reduce by warp 0
    if (blockIdx.x == 0) {
        float pacc = 0.f;
        const int kb = wid * 32;
#pragma unroll
        for (int kk = 0; kk < 32; kk++)
            pacc = fmaf(b2[kb + kk], w3s[(kb + kk) * 32 + lane], pacc);
        bpart[wid][lane] = pacc;
        __syncthreads();
        if (wid == 0) {
            float bacc = (lane < L_) ? b3[lane] : 0.f;
#pragma unroll
            for (int w = 0; w < 16; w++) bacc += bpart[w][lane];
            g_b23[lane] = bacc;
        }
    }
}

// ======================= stage 2: Wc = W1 @ W23 (+bc) =======================
// grid 96, 512thr: 16 warps x 1 row = 16 rows/CTA; 4-way k-partial ILP
__global__ __launch_bounds__(512) void k_wc(const float* __restrict__ W1,
                                            const float* __restrict__ b1) {
    extern __shared__ float s[];
    float* w23s = s;                  // [1024*32] 128KB
    float* w1s  = s + FH_ * 32;       // [16*1024]  64KB
    __shared__ float bpart[16][32];
    const int tid = threadIdx.x;
    const int wid = tid >> 5, lane = tid & 31;
    const int row0 = blockIdx.x * 16;

    {
        const uint32_t sa = smem_u32(w23s);
        const float* g = g_W23;
#pragma unroll
        for (int j = 0; j < 16; j++) {           // 8192 cp16
            int c = tid + j * 512;
            CP16(sa + (uint32_t)c * 16, g + c * 4);
        }
        const uint32_t sb = smem_u32(w1s);
        const float* g1 = W1 + (size_t)row0 * FH_;
#pragma unroll
        for (int j = 0; j < 8; j++) {            // 4096 cp16
            int c = tid + j * 512;
            CP16(sb + (uint32_t)c * 16, g1 + c * 4);
        }
        CP_COMMIT(); CP_WAIT0();
    }
    __syncthreads();

    const float* a = w1s + wid * FH_;
    float p0 = 0.f, p1 = 0.f, p2 = 0.f, p3 = 0.f;
#pragma unroll 4
    for (int k = 0; k < FH_; k += 16) {
        float4 v0 = *(const float4*)&a[k];
        float4 v1 = *(const float4*)&a[k + 4];
        float4 v2 = *(const float4*)&a[k + 8];
        float4 v3 = *(const float4*)&a[k + 12];
        p0 = fmaf(v0.x, w23s[(k + 0) * 32 + lane], p0);
        p0 = fmaf(v0.y, w23s[(k + 1) * 32 + lane], p0);
        p0 = fmaf(v0.z, w23s[(k + 2) * 32 + lane], p0);
        p0 = fmaf(v0.w, w23s[(k + 3) * 32 + lane], p0);
        p1 = fmaf(v1.x, w23s[(k + 4) * 32 + lane], p1);
        p1 = fmaf(v1.y, w23s[(k + 5) * 32 + lane], p1);
        p1 = fmaf(v1.z, w23s[(k + 6) * 32 + lane], p1);
        p1 = fmaf(v1.w, w23s[(k + 7) * 32 + lane], p1);
        p2 = fmaf(v2.x, w23s[(k + 8) * 32 + lane], p2);
        p2 = fmaf(v2.y, w23s[(k + 9) * 32 + lane], p2);
        p2 = fmaf(v2.z, w23s[(k + 10) * 32 + lane], p2);
        p2 = fmaf(v2.w, w23s[(k + 11) * 32 + lane], p2);
        p3 = fmaf(v3.x, w23s[(k + 12) * 32 + lane], p3);
        p3 = fmaf(v3.y, w23s[(k + 13) * 32 + lane], p3);
        p3 = fmaf(v3.z, w23s[(k + 14) * 32 + lane], p3);
        p3 = fmaf(v3.w, w23s[(k + 15) * 32 + lane], p3);
    }
    g_Wc[(row0 + wid) * 32 + lane] = (p0 + p1) + (p2 + p3);

    // bc on CTA 0: 16 warps x 64-k partials, fixed-order reduce
    if (blockIdx.x == 0) {
        float pacc = 0.f;
        const int kb = wid * 64;
#pragma unroll
        for (int kk = 0; kk < 64; kk++)
            pacc = fmaf(b1[kb + kk], w23s[(kb + kk) * 32 + lane], pacc);
        bpart[wid][lane] = pacc;
        __syncthreads();
        if (wid == 0) {
            float bacc = g_b23[lane];
#pragma unroll
            for (int w = 0; w < 16; w++) bacc += bpart[w][lane];
            g_bc[lane] = bacc;
        }
    }
}

// ======================= stage 3: fused gather + pq + logits + loss + final =======================
// grid 128, 256thr: 8 warps x 2 rows = 16 rows/CTA (half a batch)
__global__ __launch_bounds__(256) void k_main(const float* __restrict__ te,
                                              const int* __restrict__ pos,
                                              const float* __restrict__ labels,
                                              const float* __restrict__ pooler,
                                              float* __restrict__ out, int out_size) {
    extern __shared__ float s[];
    float* wct = s;                   // [768*32]  96KB
    float* as  = s + H_ * 32;         // [16*768]  48KB
    __shared__ float pqs[8][32];
    __shared__ float sml[8][5];
    __shared__ float red[128][5];
    __shared__ unsigned s_done;
    const int tid = threadIdx.x;
    const int wid = tid >> 5, lane = tid & 31;
    const int r0 = blockIdx.x * 16;
    const int batch = blockIdx.x >> 1;

    // issue staging (wct + 16 gathered A rows)
    {
        const uint32_t sa = smem_u32(wct);
        const float* g = g_Wc;
#pragma unroll
        for (int j = 0; j < 24; j++) {           // 6144 cp16
            int c = tid + j * 256;
            CP16(sa + (uint32_t)c * 16, g + c * 4);
        }
        const uint32_t sb = smem_u32(as);
#pragma unroll
        for (int j = 0; j < 12; j++) {           // 3072 cp16 (192 per row)
            int c = tid + j * 256;
            int row = c / 192, ch = c % 192;
            const float* src = te + ((size_t)batch * S_ + pos[r0 + row]) * H_ + ch * 4;
            CP16(sb + (uint32_t)(row * H_ + ch * 4) * 4, src);
        }
        CP_COMMIT();
    }

    // pq for this batch, overlapped with staging (reads global/L2 only)
    {
        const float* wcb = g_Wc + H_ * 32;
        const float* prow = pooler + (size_t)batch * H_;
        const int kb = wid * 96;
        float pacc = 0.f;
#pragma unroll
        for (int kk = 0; kk < 96; kk += 4) {
            float4 a4 = *(const float4*)&prow[kb + kk];
            pacc = fmaf(a4.x, wcb[(kb + kk + 0) * 32 + lane], pacc);
            pacc = fmaf(a4.y, wcb[(kb + kk + 1) * 32 + lane], pacc);
            pacc = fmaf(a4.z, wcb[(kb + kk + 2) * 32 + lane], pacc);
            pacc = fmaf(a4.w, wcb[(kb + kk + 3) * 32 + lane], pacc);
        }
        pqs[wid][lane] = pacc;
    }
    CP_WAIT0();
    __syncthreads();
    const float pqv = (((pqs[0][lane] + pqs[1][lane]) + (pqs[2][lane] + pqs[3][lane]))
                    +  ((pqs[4][lane] + pqs[5][lane]) + (pqs[6][lane] + pqs[7][lane])))
                    + g_bc[lane];

    // 2 rows per warp, 2 k-partials each (4 independent FMA chains)
    const float* a0 = as + (wid * 2 + 0) * H_;
    const float* a1 = as + (wid * 2 + 1) * H_;
    float q00 = 0.f, q01 = 0.f, q10 = 0.f, q11 = 0.f;
#pragma unroll 4
    for (int k = 0; k < H_; k += 8) {
        float4 u0 = *(const float4*)&a0[k];
        float4 u1 = *(const float4*)&a0[k + 4];
        float4 v0 = *(const float4*)&a1[k];
        float4 v1 = *(const float4*)&a1[k + 4];
        float w0 = wct[(k + 0) * 32 + lane];
        float w1 = wct[(k + 1) * 32 + lane];
        float w2 = wct[(k + 2) * 32 + lane];
        float w3 = wct[(k + 3) * 32 + lane];
        float w4 = wct[(k + 4) * 32 + lane];
        float w5 = wct[(k + 5) * 32 + lane];
        float w6 = wct[(k + 6) * 32 + lane];
        float w7 = wct[(k + 7) * 32 + lane];
        q00 = fmaf(u0.x, w0, q00); q00 = fmaf(u0.y, w1, q00);
        q00 = fmaf(u0.z, w2, q00); q00 = fmaf(u0.w, w3, q00);
        q01 = fmaf(u1.x, w4, q01); q01 = fmaf(u1.y, w5, q01);
        q01 = fmaf(u1.z, w6, q01); q01 = fmaf(u1.w, w7, q01);
        q10 = fmaf(v0.x, w0, q10); q10 = fmaf(v0.y, w1, q10);
        q10 = fmaf(v0.z, w2, q10); q10 = fmaf(v0.w, w3, q10);
        q11 = fmaf(v1.x, w4, q11); q11 = fmaf(v1.y, w5, q11);
        q11 = fmaf(v1.z, w6, q11); q11 = fmaf(v1.w, w7, q11);
    }
    float acc[2] = { q00 + q01, q10 + q11 };

    const bool active = (lane < L_);
    float st0 = 0.f, st1 = 0.f, st2 = 0.f, st3 = 0.f, st4 = 0.f;
#pragma unroll
    for (int r = 0; r < 2; r++) {
        int gr = r0 + wid * 2 + r;
        float x = acc[r] + pqv;
        float y = active ? labels[(size_t)gr * L_ + lane] : -1.0f;

        unsigned ball_bin  = __ballot_sync(0xffffffffu, active && (x > 0.f));
        unsigned ball_one  = __ballot_sync(0xffffffffu, active && (y > 0.5f));
        unsigned ball_real = __ballot_sync(0xffffffffu, active && (y != -1.0f));

        float sp  = fmaxf(x, 0.f) + log1pf(expf(-fabsf(x)));
        float bce = active ? (sp - x * y) : 0.f;
#pragma unroll
        for (int o = 16; o; o >>= 1) bce += __shfl_xor_sync(0xffffffffu, bce, o);

        if (lane == 0) {
            float mf = (ball_real != 0u) ? 1.f : 0.f;
            int co = __popc(ball_bin);
            int cl = __popc(ball_one);
            float cd = (float)(co - cl);
            bool eq = (mf != 0.f) && (co == 1) && (cl == 1);
            float pd = eq ? (float)(__ffs(ball_bin) - __ffs(ball_one)) : 0.f;
            st0 += mf * bce;
            st1 += mf;
            st2 += mf * cd * cd;
            st3 += pd * pd;
            st4 += eq ? 1.f : 0.f;
        }
    }
    if (lane == 0) {
        sml[wid][0] = st0; sml[wid][1] = st1; sml[wid][2] = st2;
        sml[wid][3] = st3; sml[wid][4] = st4;
    }
    __syncthreads();
    if (tid < 5) {
        float ssum = 0.f;
        for (int w = 0; w < 8; w++) ssum += sml[w][tid];   // fixed order
        g_part[blockIdx.x * 5 + tid] = ssum;
    }

    // ---- last-block final reduction (deterministic: fixed-order tree) ----
    __threadfence();
    __syncthreads();
    if (tid == 0) s_done = atomicAdd(&g_done, 1u);
    __syncthreads();
    if (s_done == 127u) {
        __threadfence();
        if (tid < 128)
            for (int c = 0; c < 5; c++) red[tid][c] = g_part[tid * 5 + c];
        __syncthreads();
        for (int st = 64; st > 0; st >>= 1) {
            if (tid < st)
                for (int c = 0; c < 5; c++) red[tid][c] += red[tid + st][c];
            __syncthreads();
        }
        if (tid == 0) {
            float bce_loss   = red[0][0] / (red[0][1] * (float)L_);
            float count_loss = red[0][2] / (float)MROWS;
            float pos_loss   = (red[0][4] > 0.f) ? (red[0][3] / red[0][4]) : 0.f;
            float loss = bce_loss + 10.f * count_loss + 5.f * pos_loss;
            for (int i = 0; i < out_size; i++) out[i] = loss;
        }
    }
}

// ======================= launch =======================
extern "C" void kernel_launch(void* const* d_in, const int* in_sizes, int n_in,
                              void* d_out, int out_size)
{
    const float* te   = (const float*)d_in[0];
    const float* pool = (const float*)d_in[1];
    const int*   pos  = (const int*)  d_in[2];
    const float* lab  = (const float*)d_in[3];
    const float* W1   = (const float*)d_in[4];
    const float* b1   = (const float*)d_in[5];
    const float* W2   = (const float*)d_in[6];
    const float* b2   = (const float*)d_in[7];
    const float* W3   = (const float*)d_in[8];
    const float* b3   = (const float*)d_in[9];

    const int SM_W23  = (512 * 32 + 16 * 512) * 4;     //  98304
    const int SM_WC   = (FH_ * 32 + 16 * FH_) * 4;     // 196608
    const int SM_MAIN = (H_ * 32 + 16 * H_) * 4;       // 147456

    cudaFuncSetAttribute(k_w23,  cudaFuncAttributeMaxDynamicSharedMemorySize, SM_W23);
    cudaFuncSetAttribute(k_wc,   cudaFuncAttributeMaxDynamicSharedMemorySize, SM_WC);
    cudaFuncSetAttribute(k_main, cudaFuncAttributeMaxDynamicSharedMemorySize, SM_MAIN);

    k_w23<<<FH_ / 16, 512, SM_W23>>>(W2, W3, b2, b3);   // W23, b23 (+reset counter)
    k_wc<<<(2 * H_) / 16, 512, SM_WC>>>(W1, b1);        // Wc, bc
    k_main<<<MROWS / 16, 256, SM_MAIN>>>(te, pos, lab, pool,
                                         (float*)d_out, out_size);
}

// round 13
// speedup vs baseline: 2.3036x; 1.0061x over previous
#include <cuda_runtime.h>
#include <math.h>
#include <stdint.h>

#define B_   64
#define S_   512
#define P_   32
#define L_   30
#define H_   768
#define FH_  1024
#define MROWS (B_*P_)   // 2048

// ======================= device scratch (no allocation) =======================
__device__ float g_W23[FH_ * 32];      // W2@W3, padded cols  [1024][32]
__device__ float g_Wc[2 * H_ * 32];    // W1@W23              [1536][32]
__device__ float g_b23[32];            // b2@W3 + b3
__device__ float g_bc[32];             // b1@W23 + b23
__device__ float g_part[128 * 5];
__device__ unsigned g_done;

__device__ __forceinline__ uint32_t smem_u32(const void* p) {
    uint32_t a;
    asm("{ .reg .u64 t; cvta.to.shared.u64 t, %1; cvt.u32.u64 %0, t; }"
        : "=r"(a) : "l"(p));
    return a;
}
#define CP16(dst_u32, src_ptr) \
    asm volatile("cp.async.cg.shared.global [%0], [%1], 16;" \
        :: "r"(dst_u32), "l"(src_ptr))
#define CP_COMMIT() asm volatile("cp.async.commit_group;")
#define CP_WAIT0()  asm volatile("cp.async.wait_group 0;")

// ======================= stage 1: W23 = W2 @ W3 (+b23) =======================
// grid 64, 512thr: 16 warps x 1 row = 16 rows/CTA; 4-way k-partial ILP
__global__ __launch_bounds__(512) void k_w23(const float* __restrict__ W2,
                                             const float* __restrict__ W3,
                                             const float* __restrict__ b2,
                                             const float* __restrict__ b3) {
    extern __shared__ float s[];
    float* w3s = s;                  // [512*32] 64KB
    float* w2s = s + 512 * 32;       // [16*512] 32KB
    __shared__ float bpart[16][32];
    const int tid = threadIdx.x;
    const int wid = tid >> 5, lane = tid & 31;
    const int row0 = blockIdx.x * 16;

    if (blockIdx.x == 0 && tid == 0) g_done = 0;   // reset final-reduce counter

    // stage W3 -> padded [512][32]
    for (int idx = tid; idx < 512 * 32; idx += 512) {
        int k2 = idx >> 5, l = idx & 31;
        w3s[idx] = (l < L_) ? W3[k2 * L_ + l] : 0.f;
    }
    // stage 16 W2 rows (2048 cp16)
    {
        const uint32_t sa = smem_u32(w2s);
        const float* g = W2 + (size_t)row0 * 512;
#pragma unroll
        for (int j = 0; j < 4; j++) {
            int c = tid + j * 512;
            CP16(sa + (uint32_t)c * 16, g + c * 4);
        }
        CP_COMMIT(); CP_WAIT0();
    }
    __syncthreads();

    const float* a = w2s + wid * 512;
    float p0 = 0.f, p1 = 0.f, p2 = 0.f, p3 = 0.f;
#pragma unroll 4
    for (int k = 0; k < 512; k += 16) {
        float4 v0 = *(const float4*)&a[k];
        float4 v1 = *(const float4*)&a[k + 4];
        float4 v2 = *(const float4*)&a[k + 8];
        float4 v3 = *(const float4*)&a[k + 12];
        p0 = fmaf(v0.x, w3s[(k + 0) * 32 + lane], p0);
        p0 = fmaf(v0.y, w3s[(k + 1) * 32 + lane], p0);
        p0 = fmaf(v0.z, w3s[(k + 2) * 32 + lane], p0);
        p0 = fmaf(v0.w, w3s[(k + 3) * 32 + lane], p0);
        p1 = fmaf(v1.x, w3s[(k + 4) * 32 + lane], p1);
        p1 = fmaf(v1.y, w3s[(k + 5) * 32 + lane], p1);
        p1 = fmaf(v1.z, w3s[(k + 6) * 32 + lane], p1);
        p1 = fmaf(v1.w, w3s[(k + 7) * 32 + lane], p1);
        p2 = fmaf(v2.x, w3s[(k + 8) * 32 + lane], p2);
        p2 = fmaf(v2.y, w3s[(k + 9) * 32 + lane], p2);
        p2 = fmaf(v2.z, w3s[(k + 10) * 32 + lane], p2);
        p2 = fmaf(v2.w, w3s[(k + 11) * 32 + lane], p2);
        p3 = fmaf(v3.x, w3s[(k + 12) * 32 + lane], p3);
        p3 = fmaf(v3.y, w3s[(k + 13) * 32 + lane], p3);
        p3 = fmaf(v3.z, w3s[(k + 14) * 32 + lane], p3);
        p3 = fmaf(v3.w, w3s[(k + 15) * 32 + lane], p3);
    }
    g_W23[(row0 + wid) * 32 + lane] = (p0 + p1) + (p2 + p3);

    // b23 on CTA 0: 16 warps x 32-k partials, fixed-order reduce by warp 0
    if (blockIdx.x == 0) {
        float pacc = 0.f;
        const int kb = wid * 32;
#pragma unroll
        for (int kk = 0; kk < 32; kk++)
            pacc = fmaf(b2[kb + kk], w3s[(kb + kk) * 32 + lane], pacc);
        bpart[wid][lane] = pacc;
        __syncthreads();
        if (wid == 0) {
            float bacc = (lane < L_) ? b3[lane] : 0.f;
#pragma unroll
            for (int w = 0; w < 16; w++) bacc += bpart[w][lane];
            g_b23[lane] = bacc;
        }
    }
}

// ======================= stage 2: Wc = W1 @ W23 (+bc) =======================
// grid 96, 512thr: 16 warps x 1 row = 16 rows/CTA; 4-way k-partial ILP
__global__ __launch_bounds__(512) void k_wc(const float* __restrict__ W1,
                                            const float* __restrict__ b1) {
    extern __shared__ float s[];
    float* w23s = s;                  // [1024*32] 128KB
    float* w1s  = s + FH_ * 32;       // [16*1024]  64KB
    __shared__ float bpart[16][32];
    const int tid = threadIdx.x;
    const int wid = tid >> 5, lane = tid & 31;
    const int row0 = blockIdx.x * 16;

    {
        const uint32_t sa = smem_u32(w23s);
        const float* g = g_W23;
#pragma unroll
        for (int j = 0; j < 16; j++) {           // 8192 cp16
            int c = tid + j * 512;
            CP16(sa + (uint32_t)c * 16, g + c * 4);
        }
        const uint32_t sb = smem_u32(w1s);
        const float* g1 = W1 + (size_t)row0 * FH_;
#pragma unroll
        for (int j = 0; j < 8; j++) {            // 4096 cp16
            int c = tid + j * 512;
            CP16(sb + (uint32_t)c * 16, g1 + c * 4);
        }
        CP_COMMIT(); CP_WAIT0();
    }
    __syncthreads();

    const float* a = w1s + wid * FH_;
    float p0 = 0.f, p1 = 0.f, p2 = 0.f, p3 = 0.f;
#pragma unroll 4
    for (int k = 0; k < FH_; k += 16) {
        float4 v0 = *(const float4*)&a[k];
        float4 v1 = *(const float4*)&a[k + 4];
        float4 v2 = *(const float4*)&a[k + 8];
        float4 v3 = *(const float4*)&a[k + 12];
        p0 = fmaf(v0.x, w23s[(k + 0) * 32 + lane], p0);
        p0 = fmaf(v0.y, w23s[(k + 1) * 32 + lane], p0);
        p0 = fmaf(v0.z, w23s[(k + 2) * 32 + lane], p0);
        p0 = fmaf(v0.w, w23s[(k + 3) * 32 + lane], p0);
        p1 = fmaf(v1.x, w23s[(k + 4) * 32 + lane], p1);
        p1 = fmaf(v1.y, w23s[(k + 5) * 32 + lane], p1);
        p1 = fmaf(v1.z, w23s[(k + 6) * 32 + lane], p1);
        p1 = fmaf(v1.w, w23s[(k + 7) * 32 + lane], p1);
        p2 = fmaf(v2.x, w23s[(k + 8) * 32 + lane], p2);
        p2 = fmaf(v2.y, w23s[(k + 9) * 32 + lane], p2);
        p2 = fmaf(v2.z, w23s[(k + 10) * 32 + lane], p2);
        p2 = fmaf(v2.w, w23s[(k + 11) * 32 + lane], p2);
        p3 = fmaf(v3.x, w23s[(k + 12) * 32 + lane], p3);
        p3 = fmaf(v3.y, w23s[(k + 13) * 32 + lane], p3);
        p3 = fmaf(v3.z, w23s[(k + 14) * 32 + lane], p3);
        p3 = fmaf(v3.w, w23s[(k + 15) * 32 + lane], p3);
    }
    g_Wc[(row0 + wid) * 32 + lane] = (p0 + p1) + (p2 + p3);

    // bc on CTA 0: 16 warps x 64-k partials, fixed-order reduce
    if (blockIdx.x == 0) {
        float pacc = 0.f;
        const int kb = wid * 64;
#pragma unroll
        for (int kk = 0; kk < 64; kk++)
            pacc = fmaf(b1[kb + kk], w23s[(kb + kk) * 32 + lane], pacc);
        bpart[wid][lane] = pacc;
        __syncthreads();
        if (wid == 0) {
            float bacc = g_b23[lane];
#pragma unroll
            for (int w = 0; w < 16; w++) bacc += bpart[w][lane];
            g_bc[lane] = bacc;
        }
    }
}

// ======================= stage 3: fused gather + pq + logits + loss + final =======================
// grid 128, 256thr: 8 warps x 2 rows = 16 rows/CTA (half a batch)
__global__ __launch_bounds__(256) void k_main(const float* __restrict__ te,
                                              const int* __restrict__ pos,
                                              const float* __restrict__ labels,
                                              const float* __restrict__ pooler,
                                              float* __restrict__ out, int out_size) {
    extern __shared__ float s[];
    float* wct = s;                   // [768*32]  96KB
    float* as  = s + H_ * 32;         // [16*768]  48KB
    __shared__ float pqs[8][32];
    __shared__ float sml[8][5];
    __shared__ float red[128][5];
    __shared__ unsigned s_done;
    const int tid = threadIdx.x;
    const int wid = tid >> 5, lane = tid & 31;
    const int r0 = blockIdx.x * 16;
    const int batch = blockIdx.x >> 1;

    // issue staging (wct + 16 gathered A rows)
    {
        const uint32_t sa = smem_u32(wct);
        const float* g = g_Wc;
#pragma unroll
        for (int j = 0; j < 24; j++) {           // 6144 cp16
            int c = tid + j * 256;
            CP16(sa + (uint32_t)c * 16, g + c * 4);
        }
        const uint32_t sb = smem_u32(as);
#pragma unroll
        for (int j = 0; j < 12; j++) {           // 3072 cp16 (192 per row)
            int c = tid + j * 256;
            int row = c / 192, ch = c % 192;
            const float* src = te + ((size_t)batch * S_ + pos[r0 + row]) * H_ + ch * 4;
            CP16(sb + (uint32_t)(row * H_ + ch * 4) * 4, src);
        }
        CP_COMMIT();
    }

    // pq for this batch, overlapped with staging (reads global/L2 only)
    {
        const float* wcb = g_Wc + H_ * 32;
        const float* prow = pooler + (size_t)batch * H_;
        const int kb = wid * 96;
        float pacc = 0.f;
#pragma unroll
        for (int kk = 0; kk < 96; kk += 4) {
            float4 a4 = *(const float4*)&prow[kb + kk];
            pacc = fmaf(a4.x, wcb[(kb + kk + 0) * 32 + lane], pacc);
            pacc = fmaf(a4.y, wcb[(kb + kk + 1) * 32 + lane], pacc);
            pacc = fmaf(a4.z, wcb[(kb + kk + 2) * 32 + lane], pacc);
            pacc = fmaf(a4.w, wcb[(kb + kk + 3) * 32 + lane], pacc);
        }
        pqs[wid][lane] = pacc;
    }
    CP_WAIT0();
    __syncthreads();
    const float pqv = (((pqs[0][lane] + pqs[1][lane]) + (pqs[2][lane] + pqs[3][lane]))
                    +  ((pqs[4][lane] + pqs[5][lane]) + (pqs[6][lane] + pqs[7][lane])))
                    + g_bc[lane];

    // 2 rows per warp, 2 k-partials each (4 independent FMA chains)
    const float* a0 = as + (wid * 2 + 0) * H_;
    const float* a1 = as + (wid * 2 + 1) * H_;
    float q00 = 0.f, q01 = 0.f, q10 = 0.f, q11 = 0.f;
#pragma unroll 4
    for (int k = 0; k < H_; k += 8) {
        float4 u0 = *(const float4*)&a0[k];
        float4 u1 = *(const float4*)&a0[k + 4];
        float4 v0 = *(const float4*)&a1[k];
        float4 v1 = *(const float4*)&a1[k + 4];
        float w0 = wct[(k + 0) * 32 + lane];
        float w1 = wct[(k + 1) * 32 + lane];
        float w2 = wct[(k + 2) * 32 + lane];
        float w3 = wct[(k + 3) * 32 + lane];
        float w4 = wct[(k + 4) * 32 + lane];
        float w5 = wct[(k + 5) * 32 + lane];
        float w6 = wct[(k + 6) * 32 + lane];
        float w7 = wct[(k + 7) * 32 + lane];
        q00 = fmaf(u0.x, w0, q00); q00 = fmaf(u0.y, w1, q00);
        q00 = fmaf(u0.z, w2, q00); q00 = fmaf(u0.w, w3, q00);
        q01 = fmaf(u1.x, w4, q01); q01 = fmaf(u1.y, w5, q01);
        q01 = fmaf(u1.z, w6, q01); q01 = fmaf(u1.w, w7, q01);
        q10 = fmaf(v0.x, w0, q10); q10 = fmaf(v0.y, w1, q10);
        q10 = fmaf(v0.z, w2, q10); q10 = fmaf(v0.w, w3, q10);
        q11 = fmaf(v1.x, w4, q11); q11 = fmaf(v1.y, w5, q11);
        q11 = fmaf(v1.z, w6, q11); q11 = fmaf(v1.w, w7, q11);
    }
    float acc[2] = { q00 + q01, q10 + q11 };

    const bool active = (lane < L_);
    float st0 = 0.f, st1 = 0.f, st2 = 0.f, st3 = 0.f, st4 = 0.f;
#pragma unroll
    for (int r = 0; r < 2; r++) {
        int gr = r0 + wid * 2 + r;
        float x = acc[r] + pqv;
        float y = active ? labels[(size_t)gr * L_ + lane] : -1.0f;

        unsigned ball_bin  = __ballot_sync(0xffffffffu, active && (x > 0.f));
        unsigned ball_one  = __ballot_sync(0xffffffffu, active && (y > 0.5f));
        unsigned ball_real = __ballot_sync(0xffffffffu, active && (y != -1.0f));

        float sp  = fmaxf(x, 0.f) + log1pf(expf(-fabsf(x)));
        float bce = active ? (sp - x * y) : 0.f;
#pragma unroll
        for (int o = 16; o; o >>= 1) bce += __shfl_xor_sync(0xffffffffu, bce, o);

        if (lane == 0) {
            float mf = (ball_real != 0u) ? 1.f : 0.f;
            int co = __popc(ball_bin);
            int cl = __popc(ball_one);
            float cd = (float)(co - cl);
            bool eq = (mf != 0.f) && (co == 1) && (cl == 1);
            float pd = eq ? (float)(__ffs(ball_bin) - __ffs(ball_one)) : 0.f;
            st0 += mf * bce;
            st1 += mf;
            st2 += mf * cd * cd;
            st3 += pd * pd;
            st4 += eq ? 1.f : 0.f;
        }
    }
    if (lane == 0) {
        sml[wid][0] = st0; sml[wid][1] = st1; sml[wid][2] = st2;
        sml[wid][3] = st3; sml[wid][4] = st4;
    }
    __syncthreads();
    if (tid < 5) {
        float ssum = 0.f;
        for (int w = 0; w < 8; w++) ssum += sml[w][tid];   // fixed order
        g_part[blockIdx.x * 5 + tid] = ssum;
    }

    // ---- last-block final reduction (deterministic: fixed-order tree) ----
    __threadfence();
    __syncthreads();
    if (tid == 0) s_done = atomicAdd(&g_done, 1u);
    __syncthreads();
    if (s_done == 127u) {
        __threadfence();
        if (tid < 128)
            for (int c = 0; c < 5; c++) red[tid][c] = g_part[tid * 5 + c];
        __syncthreads();
        for (int st = 64; st > 0; st >>= 1) {
            if (tid < st)
                for (int c = 0; c < 5; c++) red[tid][c] += red[tid + st][c];
            __syncthreads();
        }
        if (tid == 0) {
            float bce_loss   = red[0][0] / (red[0][1] * (float)L_);
            float count_loss = red[0][2] / (float)MROWS;
            float pos_loss   = (red[0][4] > 0.f) ? (red[0][3] / red[0][4]) : 0.f;
            float loss = bce_loss + 10.f * count_loss + 5.f * pos_loss;
            for (int i = 0; i < out_size; i++) out[i] = loss;
        }
    }
}

// ======================= launch =======================
extern "C" void kernel_launch(void* const* d_in, const int* in_sizes, int n_in,
                              void* d_out, int out_size)
{
    const float* te   = (const float*)d_in[0];
    const float* pool = (const float*)d_in[1];
    const int*   pos  = (const int*)  d_in[2];
    const float* lab  = (const float*)d_in[3];
    const float* W1   = (const float*)d_in[4];
    const float* b1   = (const float*)d_in[5];
    const float* W2   = (const float*)d_in[6];
    const float* b2   = (const float*)d_in[7];
    const float* W3   = (const float*)d_in[8];
    const float* b3   = (const float*)d_in[9];

    const int SM_W23  = (512 * 32 + 16 * 512) * 4;     //  98304
    const int SM_WC   = (FH_ * 32 + 16 * FH_) * 4;     // 196608
    const int SM_MAIN = (H_ * 32 + 16 * H_) * 4;       // 147456

    cudaFuncSetAttribute(k_w23,  cudaFuncAttributeMaxDynamicSharedMemorySize, SM_W23);
    cudaFuncSetAttribute(k_wc,   cudaFuncAttributeMaxDynamicSharedMemorySize, SM_WC);
    cudaFuncSetAttribute(k_main, cudaFuncAttributeMaxDynamicSharedMemorySize, SM_MAIN);

    k_w23<<<FH_ / 16, 512, SM_W23>>>(W2, W3, b2, b3);   // W23, b23 (+reset counter)
    k_wc<<<(2 * H_) / 16, 512, SM_WC>>>(W1, b1);        // Wc, bc
    k_main<<<MROWS / 16, 256, SM_MAIN>>>(te, pos, lab, pool,
                                         (float*)d_out, out_size);
}

// round 14
// speedup vs baseline: 2.3942x; 1.0394x over previous
#include <cuda_runtime.h>
#include <math.h>
#include <stdint.h>

#define B_   64
#define S_   512
#define P_   32
#define L_   30
#define H_   768
#define FH_  1024
#define MROWS (B_*P_)   // 2048

// ======================= device scratch (no allocation) =======================
__device__ float g_W23[FH_ * 32];      // W2@W3 (lanes 30/31 garbage, masked)
__device__ float g_Wc[2 * H_ * 32];    // W1@W23
__device__ float g_b23[32];
__device__ float g_bc[32];
__device__ float g_part[128 * 5];
__device__ unsigned g_done;

__device__ __forceinline__ uint32_t smem_u32(const void* p) {
    uint32_t a;
    asm("{ .reg .u64 t; cvta.to.shared.u64 t, %1; cvt.u32.u64 %0, t; }"
        : "=r"(a) : "l"(p));
    return a;
}
#define CP16(dst_u32, src_ptr) \
    asm volatile("cp.async.cg.shared.global [%0], [%1], 16;" \
        :: "r"(dst_u32), "l"(src_ptr))
#define CP_COMMIT() asm volatile("cp.async.commit_group;")
#define CP_WAIT0()  asm volatile("cp.async.wait_group 0;")

// ======================= stage 1: W23 = W2 @ W3 (+b23) =======================
// grid 64, 512thr: 16 warps x 1 row; W3 staged PACKED (stride 30) via cp.async
__global__ __launch_bounds__(512) void k_w23(const float* __restrict__ W2,
                                             const float* __restrict__ W3,
                                             const float* __restrict__ b2,
                                             const float* __restrict__ b3) {
    extern __shared__ float s[];
    float* w3s = s;                  // [512*30 + 8] packed, ~60KB
    float* w2s = s + 512 * 30 + 8;   // [16*512] 32KB
    __shared__ float bpart[16][32];
    const int tid = threadIdx.x;
    const int wid = tid >> 5, lane = tid & 31;
    const int row0 = blockIdx.x * 16;

    if (blockIdx.x == 0 && tid == 0) g_done = 0;

    // stage W3 packed: 15360 floats = 3840 cp16
    {
        const uint32_t sa = smem_u32(w3s);
#pragma unroll
        for (int j = 0; j < 8; j++) {
            int c = tid + j * 512;
            if (c < 3840) CP16(sa + (uint32_t)c * 16, W3 + c * 4);
        }
        const uint32_t sb = smem_u32(w2s);
        const float* g = W2 + (size_t)row0 * 512;
#pragma unroll
        for (int j = 0; j < 4; j++) {            // 2048 cp16
            int c = tid + j * 512;
            CP16(sb + (uint32_t)c * 16, g + c * 4);
        }
        CP_COMMIT(); CP_WAIT0();
    }
    __syncthreads();

    const float* a = w2s + wid * 512;
    float p0 = 0.f, p1 = 0.f, p2 = 0.f, p3 = 0.f;
#pragma unroll 4
    for (int k = 0; k < 512; k += 16) {
        float4 v0 = *(const float4*)&a[k];
        float4 v1 = *(const float4*)&a[k + 4];
        float4 v2 = *(const float4*)&a[k + 8];
        float4 v3 = *(const float4*)&a[k + 12];
        p0 = fmaf(v0.x, w3s[(k + 0) * 30 + lane], p0);
        p0 = fmaf(v0.y, w3s[(k + 1) * 30 + lane], p0);
        p0 = fmaf(v0.z, w3s[(k + 2) * 30 + lane], p0);
        p0 = fmaf(v0.w, w3s[(k + 3) * 30 + lane], p0);
        p1 = fmaf(v1.x, w3s[(k + 4) * 30 + lane], p1);
        p1 = fmaf(v1.y, w3s[(k + 5) * 30 + lane], p1);
        p1 = fmaf(v1.z, w3s[(k + 6) * 30 + lane], p1);
        p1 = fmaf(v1.w, w3s[(k + 7) * 30 + lane], p1);
        p2 = fmaf(v2.x, w3s[(k + 8) * 30 + lane], p2);
        p2 = fmaf(v2.y, w3s[(k + 9) * 30 + lane], p2);
        p2 = fmaf(v2.z, w3s[(k + 10) * 30 + lane], p2);
        p2 = fmaf(v2.w, w3s[(k + 11) * 30 + lane], p2);
        p3 = fmaf(v3.x, w3s[(k + 12) * 30 + lane], p3);
        p3 = fmaf(v3.y, w3s[(k + 13) * 30 + lane], p3);
        p3 = fmaf(v3.z, w3s[(k + 14) * 30 + lane], p3);
        p3 = fmaf(v3.w, w3s[(k + 15) * 30 + lane], p3);
    }
    g_W23[(row0 + wid) * 32 + lane] = (p0 + p1) + (p2 + p3);

    if (blockIdx.x == 0) {
        float pacc = 0.f;
        const int kb = wid * 32;
#pragma unroll
        for (int kk = 0; kk < 32; kk++)
            pacc = fmaf(b2[kb + kk], w3s[(kb + kk) * 30 + lane], pacc);
        bpart[wid][lane] = pacc;
        __syncthreads();
        if (wid == 0) {
            float bacc = (lane < L_) ? b3[lane] : 0.f;
#pragma unroll
            for (int w = 0; w < 16; w++) bacc += bpart[w][lane];
            g_b23[lane] = bacc;
        }
    }
}

// ======================= stage 2: Wc = W1 @ W23 (+bc) =======================
// grid 128, 384thr: 12 warps x 1 row = 12 rows/CTA
__global__ __launch_bounds__(384) void k_wc(const float* __restrict__ W1,
                                            const float* __restrict__ b1) {
    extern __shared__ float s[];
    float* w23s = s;                  // [1024*32] 128KB
    float* w1s  = s + FH_ * 32;       // [12*1024]  48KB
    __shared__ float bpart[8][32];
    const int tid = threadIdx.x;
    const int wid = tid >> 5, lane = tid & 31;
    const int row0 = blockIdx.x * 12;

    {
        const uint32_t sa = smem_u32(w23s);
        const float* g = g_W23;
#pragma unroll
        for (int j = 0; j < 22; j++) {           // 8192 cp16
            int c = tid + j * 384;
            if (c < 8192) CP16(sa + (uint32_t)c * 16, g + c * 4);
        }
        const uint32_t sb = smem_u32(w1s);
        const float* g1 = W1 + (size_t)row0 * FH_;
#pragma unroll
        for (int j = 0; j < 8; j++) {            // 3072 cp16
            int c = tid + j * 384;
            CP16(sb + (uint32_t)c * 16, g1 + c * 4);
        }
        CP_COMMIT(); CP_WAIT0();
    }
    __syncthreads();

    const float* a = w1s + wid * FH_;
    float p0 = 0.f, p1 = 0.f, p2 = 0.f, p3 = 0.f;
#pragma unroll 4
    for (int k = 0; k < FH_; k += 16) {
        float4 v0 = *(const float4*)&a[k];
        float4 v1 = *(const float4*)&a[k + 4];
        float4 v2 = *(const float4*)&a[k + 8];
        float4 v3 = *(const float4*)&a[k + 12];
        p0 = fmaf(v0.x, w23s[(k + 0) * 32 + lane], p0);
        p0 = fmaf(v0.y, w23s[(k + 1) * 32 + lane], p0);
        p0 = fmaf(v0.z, w23s[(k + 2) * 32 + lane], p0);
        p0 = fmaf(v0.w, w23s[(k + 3) * 32 + lane], p0);
        p1 = fmaf(v1.x, w23s[(k + 4) * 32 + lane], p1);
        p1 = fmaf(v1.y, w23s[(k + 5) * 32 + lane], p1);
        p1 = fmaf(v1.z, w23s[(k + 6) * 32 + lane], p1);
        p1 = fmaf(v1.w, w23s[(k + 7) * 32 + lane], p1);
        p2 = fmaf(v2.x, w23s[(k + 8) * 32 + lane], p2);
        p2 = fmaf(v2.y, w23s[(k + 9) * 32 + lane], p2);
        p2 = fmaf(v2.z, w23s[(k + 10) * 32 + lane], p2);
        p2 = fmaf(v2.w, w23s[(k + 11) * 32 + lane], p2);
        p3 = fmaf(v3.x, w23s[(k + 12) * 32 + lane], p3);
        p3 = fmaf(v3.y, w23s[(k + 13) * 32 + lane], p3);
        p3 = fmaf(v3.z, w23s[(k + 14) * 32 + lane], p3);
        p3 = fmaf(v3.w, w23s[(k + 15) * 32 + lane], p3);
    }
    g_Wc[(row0 + wid) * 32 + lane] = (p0 + p1) + (p2 + p3);

    // bc on CTA 0: 8 warps x 128-k partials, fixed-order reduce
    if (blockIdx.x == 0 && wid < 8) {
        float pacc = 0.f;
        const int kb = wid * 128;
#pragma unroll 8
        for (int kk = 0; kk < 128; kk++)
            pacc = fmaf(b1[kb + kk], w23s[(kb + kk) * 32 + lane], pacc);
        bpart[wid][lane] = pacc;
        __syncwarp();
        // warp 0 reduces after all 8 warps wrote (barrier below)
    }
    if (blockIdx.x == 0) {
        __syncthreads();
        if (wid == 0) {
            float bacc = g_b23[lane];
#pragma unroll
            for (int w = 0; w < 8; w++) bacc += bpart[w][lane];
            g_bc[lane] = bacc;
        }
    }
}

// ======================= stage 3: fused gather + pq + logits + loss + final =======================
// grid 128, 512thr: 16 warps x 1 row = 16 rows/CTA (half a batch)
__global__ __launch_bounds__(512) void k_main(const float* __restrict__ te,
                                              const int* __restrict__ pos,
                                              const float* __restrict__ labels,
                                              const float* __restrict__ pooler,
                                              float* __restrict__ out, int out_size) {
    extern __shared__ float s[];
    float* wct = s;                   // [768*32]  96KB
    float* as  = s + H_ * 32;         // [16*768]  48KB
    __shared__ float pqs[16][32];
    __shared__ float sml[16][5];
    __shared__ float red[128][5];
    __shared__ unsigned s_done;
    const int tid = threadIdx.x;
    const int wid = tid >> 5, lane = tid & 31;
    const int r0 = blockIdx.x * 16;
    const int batch = blockIdx.x >> 1;

    // issue staging (wct + 16 gathered A rows)
    {
        const uint32_t sa = smem_u32(wct);
        const float* g = g_Wc;
#pragma unroll
        for (int j = 0; j < 12; j++) {           // 6144 cp16
            int c = tid + j * 512;
            CP16(sa + (uint32_t)c * 16, g + c * 4);
        }
        const uint32_t sb = smem_u32(as);
#pragma unroll
        for (int j = 0; j < 6; j++) {            // 3072 cp16 (192 per row)
            int c = tid + j * 512;
            int row = c / 192, ch = c % 192;
            const float* src = te + ((size_t)batch * S_ + pos[r0 + row]) * H_ + ch * 4;
            CP16(sb + (uint32_t)(row * H_ + ch * 4) * 4, src);
        }
        CP_COMMIT();
    }

    // pq for this batch, overlapped with staging (global/L2 reads only)
    {
        const float* wcb = g_Wc + H_ * 32;
        const float* prow = pooler + (size_t)batch * H_;
        const int kb = wid * 48;
        float pacc = 0.f;
#pragma unroll
        for (int kk = 0; kk < 48; kk += 4) {
            float4 a4 = *(const float4*)&prow[kb + kk];
            pacc = fmaf(a4.x, wcb[(kb + kk + 0) * 32 + lane], pacc);
            pacc = fmaf(a4.y, wcb[(kb + kk + 1) * 32 + lane], pacc);
            pacc = fmaf(a4.z, wcb[(kb + kk + 2) * 32 + lane], pacc);
            pacc = fmaf(a4.w, wcb[(kb + kk + 3) * 32 + lane], pacc);
        }
        pqs[wid][lane] = pacc;
    }
    CP_WAIT0();
    __syncthreads();
    float pqv = g_bc[lane];
#pragma unroll
    for (int w = 0; w < 16; w++) pqv += pqs[w][lane];   // fixed order

    // 1 row per warp, 4 k-partials
    const float* a = as + wid * H_;
    float p0 = 0.f, p1 = 0.f, p2 = 0.f, p3 = 0.f;
#pragma unroll 4
    for (int k = 0; k < H_; k += 16) {
        float4 v0 = *(const float4*)&a[k];
        float4 v1 = *(const float4*)&a[k + 4];
        float4 v2 = *(const float4*)&a[k + 8];
        float4 v3 = *(const float4*)&a[k + 12];
        p0 = fmaf(v0.x, wct[(k + 0) * 32 + lane], p0);
        p0 = fmaf(v0.y, wct[(k + 1) * 32 + lane], p0);
        p0 = fmaf(v0.z, wct[(k + 2) * 32 + lane], p0);
        p0 = fmaf(v0.w, wct[(k + 3) * 32 + lane], p0);
        p1 = fmaf(v1.x, wct[(k + 4) * 32 + lane], p1);
        p1 = fmaf(v1.y, wct[(k + 5) * 32 + lane], p1);
        p1 = fmaf(v1.z, wct[(k + 6) * 32 + lane], p1);
        p1 = fmaf(v1.w, wct[(k + 7) * 32 + lane], p1);
        p2 = fmaf(v2.x, wct[(k + 8) * 32 + lane], p2);
        p2 = fmaf(v2.y, wct[(k + 9) * 32 + lane], p2);
        p2 = fmaf(v2.z, wct[(k + 10) * 32 + lane], p2);
        p2 = fmaf(v2.w, wct[(k + 11) * 32 + lane], p2);
        p3 = fmaf(v3.x, wct[(k + 12) * 32 + lane], p3);
        p3 = fmaf(v3.y, wct[(k + 13) * 32 + lane], p3);
        p3 = fmaf(v3.z, wct[(k + 14) * 32 + lane], p3);
        p3 = fmaf(v3.w, wct[(k + 15) * 32 + lane], p3);
    }
    float x = ((p0 + p1) + (p2 + p3)) + pqv;

    const bool active = (lane < L_);
    const int gr = r0 + wid;
    float y = active ? labels[(size_t)gr * L_ + lane] : -1.0f;

    unsigned ball_bin  = __ballot_sync(0xffffffffu, active && (x > 0.f));
    unsigned ball_one  = __ballot_sync(0xffffffffu, active && (y > 0.5f));
    unsigned ball_real = __ballot_sync(0xffffffffu, active && (y != -1.0f));

    float sp  = fmaxf(x, 0.f) + log1pf(expf(-fabsf(x)));
    float bce = active ? (sp - x * y) : 0.f;
#pragma unroll
    for (int o = 16; o; o >>= 1) bce += __shfl_xor_sync(0xffffffffu, bce, o);

    if (lane == 0) {
        float mf = (ball_real != 0u) ? 1.f : 0.f;
        int co = __popc(ball_bin);
        int cl = __popc(ball_one);
        float cd = (float)(co - cl);
        bool eq = (mf != 0.f) && (co == 1) && (cl == 1);
        float pd = eq ? (float)(__ffs(ball_bin) - __ffs(ball_one)) : 0.f;
        sml[wid][0] = mf * bce;
        sml[wid][1] = mf;
        sml[wid][2] = mf * cd * cd;
        sml[wid][3] = pd * pd;
        sml[wid][4] = eq ? 1.f : 0.f;
    }
    __syncthreads();
    if (tid < 5) {
        float ssum = 0.f;
        for (int w = 0; w < 16; w++) ssum += sml[w][tid];   // fixed order
        g_part[blockIdx.x * 5 + tid] = ssum;
    }

    // ---- last-block final reduction (deterministic fixed-order tree) ----
    __threadfence();
    __syncthreads();
    if (tid == 0) s_done = atomicAdd(&g_done, 1u);
    __syncthreads();
    if (s_done == 127u) {
        __threadfence();
        if (tid < 128)
            for (int c = 0; c < 5; c++) red[tid][c] = g_part[tid * 5 + c];
        __syncthreads();
        for (int st = 64; st > 0; st >>= 1) {
            if (tid < st)
                for (int c = 0; c < 5; c++) red[tid][c] += red[tid + st][c];
            __syncthreads();
        }
        if (tid == 0) {
            float bce_loss   = red[0][0] / (red[0][1] * (float)L_);
            float count_loss = red[0][2] / (float)MROWS;
            float pos_loss   = (red[0][4] > 0.f) ? (red[0][3] / red[0][4]) : 0.f;
            float loss = bce_loss + 10.f * count_loss + 5.f * pos_loss;
            for (int i = 0; i < out_size; i++) out[i] = loss;
        }
    }
}

// ======================= launch =======================
extern "C" void kernel_launch(void* const* d_in, const int* in_sizes, int n_in,
                              void* d_out, int out_size)
{
    const float* te   = (const float*)d_in[0];
    const float* pool = (const float*)d_in[1];
    const int*   pos  = (const int*)  d_in[2];
    const float* lab  = (const float*)d_in[3];
    const float* W1   = (const float*)d_in[4];
    const float* b1   = (const float*)d_in[5];
    const float* W2   = (const float*)d_in[6];
    const float* b2   = (const float*)d_in[7];
    const float* W3   = (const float*)d_in[8];
    const float* b3   = (const float*)d_in[9];

    const int SM_W23  = (512 * 30 + 8 + 16 * 512) * 4;   //  94240
    const int SM_WC   = (FH_ * 32 + 12 * FH_) * 4;       // 180224
    const int SM_MAIN = (H_ * 32 + 16 * H_) * 4;         // 147456

    cudaFuncSetAttribute(k_w23,  cudaFuncAttributeMaxDynamicSharedMemorySize, SM_W23);
    cudaFuncSetAttribute(k_wc,   cudaFuncAttributeMaxDynamicSharedMemorySize, SM_WC);
    cudaFuncSetAttribute(k_main, cudaFuncAttributeMaxDynamicSharedMemorySize, SM_MAIN);

    k_w23<<<FH_ / 16, 512, SM_W23>>>(W2, W3, b2, b3);   // W23, b23 (+reset counter)
    k_wc<<<(2 * H_) / 12, 384, SM_WC>>>(W1, b1);        // Wc, bc
    k_main<<<MROWS / 16, 512, SM_MAIN>>>(te, pos, lab, pool,
                                         (float*)d_out, out_size);
}

// round 15
// speedup vs baseline: 2.6147x; 1.0921x over previous
#include <cuda_runtime.h>
#include <math.h>
#include <stdint.h>

#define B_   64
#define S_   512
#define P_   32
#define L_   30
#define H_   768
#define FH_  1024
#define MROWS (B_*P_)   // 2048

// ======================= device scratch (no allocation) =======================
__device__ float g_W23[FH_ * 32];      // W2@W3 (lanes 30/31 garbage, masked)
__device__ float g_Wc[2 * H_ * 32];    // W1@W23
__device__ float g_b23[32];
__device__ float g_bc[32];
__device__ float g_part[128 * 5];
__device__ unsigned g_done;

__device__ __forceinline__ uint32_t smem_u32(const void* p) {
    uint32_t a;
    asm("{ .reg .u64 t; cvta.to.shared.u64 t, %1; cvt.u32.u64 %0, t; }"
        : "=r"(a) : "l"(p));
    return a;
}
#define CP16(dst_u32, src_ptr) \
    asm volatile("cp.async.cg.shared.global [%0], [%1], 16;" \
        :: "r"(dst_u32), "l"(src_ptr))
#define CP_COMMIT() asm volatile("cp.async.commit_group;")
#define CP_WAIT0()  asm volatile("cp.async.wait_group 0;")

// ======================= stage 1: W23 = W2 @ W3 (+b23) =======================
// grid 128, 512thr: 16 warps = 8 rows x 2 K-halves (split-K2, smem combine)
__global__ __launch_bounds__(512) void k_w23(const float* __restrict__ W2,
                                             const float* __restrict__ W3,
                                             const float* __restrict__ b2,
                                             const float* __restrict__ b3) {
    extern __shared__ float s[];
    float* w3s = s;                  // [512*30+8] packed ~60KB
    float* w2s = s + 512 * 30 + 8;   // [8*512] 16KB
    __shared__ float ppart[16][32];
    __shared__ float bpart[16][32];
    const int tid = threadIdx.x;
    const int wid = tid >> 5, lane = tid & 31;
    const int row0 = blockIdx.x * 8;

    if (blockIdx.x == 0 && tid == 0) g_done = 0;

    // stage W3 packed (3840 cp16) + 8 W2 rows (1024 cp16)
    {
        const uint32_t sa = smem_u32(w3s);
#pragma unroll
        for (int j = 0; j < 8; j++) {
            int c = tid + j * 512;
            if (c < 3840) CP16(sa + (uint32_t)c * 16, W3 + c * 4);
        }
        const uint32_t sb = smem_u32(w2s);
        const float* g = W2 + (size_t)row0 * 512;
#pragma unroll
        for (int j = 0; j < 2; j++) {
            int c = tid + j * 512;
            CP16(sb + (uint32_t)c * 16, g + c * 4);
        }
        CP_COMMIT(); CP_WAIT0();
    }
    __syncthreads();

    const int row = wid & 7, kh = wid >> 3;
    const float* a = w2s + row * 512 + kh * 256;
    const int kbase = kh * 256;
    float p0 = 0.f, p1 = 0.f, p2 = 0.f, p3 = 0.f;
#pragma unroll 4
    for (int k = 0; k < 256; k += 16) {
        float4 v0 = *(const float4*)&a[k];
        float4 v1 = *(const float4*)&a[k + 4];
        float4 v2 = *(const float4*)&a[k + 8];
        float4 v3 = *(const float4*)&a[k + 12];
        const float* wz = w3s + (kbase + k) * 30 + lane;
        p0 = fmaf(v0.x, wz[0 * 30], p0);
        p0 = fmaf(v0.y, wz[1 * 30], p0);
        p0 = fmaf(v0.z, wz[2 * 30], p0);
        p0 = fmaf(v0.w, wz[3 * 30], p0);
        p1 = fmaf(v1.x, wz[4 * 30], p1);
        p1 = fmaf(v1.y, wz[5 * 30], p1);
        p1 = fmaf(v1.z, wz[6 * 30], p1);
        p1 = fmaf(v1.w, wz[7 * 30], p1);
        p2 = fmaf(v2.x, wz[8 * 30], p2);
        p2 = fmaf(v2.y, wz[9 * 30], p2);
        p2 = fmaf(v2.z, wz[10 * 30], p2);
        p2 = fmaf(v2.w, wz[11 * 30], p2);
        p3 = fmaf(v3.x, wz[12 * 30], p3);
        p3 = fmaf(v3.y, wz[13 * 30], p3);
        p3 = fmaf(v3.z, wz[14 * 30], p3);
        p3 = fmaf(v3.w, wz[15 * 30], p3);
    }
    ppart[wid][lane] = (p0 + p1) + (p2 + p3);
    __syncthreads();
    if (wid < 8)
        g_W23[(row0 + wid) * 32 + lane] = ppart[wid][lane] + ppart[wid + 8][lane];

    if (blockIdx.x == 0) {
        float pacc = 0.f;
        const int kb = wid * 32;
#pragma unroll
        for (int kk = 0; kk < 32; kk++)
            pacc = fmaf(b2[kb + kk], w3s[(kb + kk) * 30 + lane], pacc);
        bpart[wid][lane] = pacc;
        __syncthreads();
        if (wid == 0) {
            float bacc = (lane < L_) ? b3[lane] : 0.f;
#pragma unroll
            for (int w = 0; w < 16; w++) bacc += bpart[w][lane];
            g_b23[lane] = bacc;
        }
    }
}

// ======================= stage 2: Wc = W1 @ W23 (+bc) =======================
// grid 128, 192thr: 6 warps x 2 rows = 12 rows/CTA (W amortized over 2 rows)
__global__ __launch_bounds__(192) void k_wc(const float* __restrict__ W1,
                                            const float* __restrict__ b1) {
    extern __shared__ float s[];
    float* w23s = s;                  // [1024*32] 128KB
    float* w1s  = s + FH_ * 32;       // [12*1024]  48KB
    __shared__ float bpart[4][32];
    const int tid = threadIdx.x;
    const int wid = tid >> 5, lane = tid & 31;
    const int row0 = blockIdx.x * 12;

    {
        const uint32_t sa = smem_u32(w23s);
        const float* g = g_W23;
#pragma unroll
        for (int j = 0; j < 43; j++) {           // 8192 cp16
            int c = tid + j * 192;
            if (c < 8192) CP16(sa + (uint32_t)c * 16, g + c * 4);
        }
        const uint32_t sb = smem_u32(w1s);
        const float* g1 = W1 + (size_t)row0 * FH_;
#pragma unroll
        for (int j = 0; j < 16; j++) {           // 3072 cp16
            int c = tid + j * 192;
            CP16(sb + (uint32_t)c * 16, g1 + c * 4);
        }
        CP_COMMIT(); CP_WAIT0();
    }
    __syncthreads();

    const float* a0 = w1s + (wid * 2 + 0) * FH_;
    const float* a1 = w1s + (wid * 2 + 1) * FH_;
    float p00 = 0.f, p01 = 0.f, p10 = 0.f, p11 = 0.f;
#pragma unroll 4
    for (int k = 0; k < FH_; k += 8) {
        float4 u0 = *(const float4*)&a0[k];
        float4 u1 = *(const float4*)&a0[k + 4];
        float4 v0 = *(const float4*)&a1[k];
        float4 v1 = *(const float4*)&a1[k + 4];
        float w0 = w23s[(k + 0) * 32 + lane];
        float w1 = w23s[(k + 1) * 32 + lane];
        float w2 = w23s[(k + 2) * 32 + lane];
        float w3 = w23s[(k + 3) * 32 + lane];
        float w4 = w23s[(k + 4) * 32 + lane];
        float w5 = w23s[(k + 5) * 32 + lane];
        float w6 = w23s[(k + 6) * 32 + lane];
        float w7 = w23s[(k + 7) * 32 + lane];
        p00 = fmaf(u0.x, w0, p00); p00 = fmaf(u0.y, w1, p00);
        p00 = fmaf(u0.z, w2, p00); p00 = fmaf(u0.w, w3, p00);
        p01 = fmaf(u1.x, w4, p01); p01 = fmaf(u1.y, w5, p01);
        p01 = fmaf(u1.z, w6, p01); p01 = fmaf(u1.w, w7, p01);
        p10 = fmaf(v0.x, w0, p10); p10 = fmaf(v0.y, w1, p10);
        p10 = fmaf(v0.z, w2, p10); p10 = fmaf(v0.w, w3, p10);
        p11 = fmaf(v1.x, w4, p11); p11 = fmaf(v1.y, w5, p11);
        p11 = fmaf(v1.z, w6, p11); p11 = fmaf(v1.w, w7, p11);
    }
    g_Wc[(row0 + wid * 2 + 0) * 32 + lane] = p00 + p01;
    g_Wc[(row0 + wid * 2 + 1) * 32 + lane] = p10 + p11;

    // bc on CTA 0: warps 0-3 x 256-k partials, fixed-order reduce
    if (blockIdx.x == 0) {
        if (wid < 4) {
            float pacc = 0.f;
            const int kb = wid * 256;
#pragma unroll 8
            for (int kk = 0; kk < 256; kk++)
                pacc = fmaf(b1[kb + kk], w23s[(kb + kk) * 32 + lane], pacc);
            bpart[wid][lane] = pacc;
        }
        __syncthreads();
        if (wid == 0) {
            float bacc = g_b23[lane];
#pragma unroll
            for (int w = 0; w < 4; w++) bacc += bpart[w][lane];
            g_bc[lane] = bacc;
        }
    }
}

// ======================= stage 3: fused gather + pq + logits + loss + final =======================
// grid 128, 256thr: 8 warps x 2 rows = 16 rows/CTA (half a batch)
__global__ __launch_bounds__(256) void k_main(const float* __restrict__ te,
                                              const int* __restrict__ pos,
                                              const float* __restrict__ labels,
                                              const float* __restrict__ pooler,
                                              float* __restrict__ out, int out_size) {
    extern __shared__ float s[];
    float* wct = s;                   // [768*32]  96KB
    float* as  = s + H_ * 32;         // [16*768]  48KB
    __shared__ float pqs[8][32];
    __shared__ float sml[8][5];
    __shared__ float red[128][5];
    __shared__ unsigned s_done;
    const int tid = threadIdx.x;
    const int wid = tid >> 5, lane = tid & 31;
    const int r0 = blockIdx.x * 16;
    const int batch = blockIdx.x >> 1;

    // issue staging (wct + 16 gathered A rows)
    {
        const uint32_t sa = smem_u32(wct);
        const float* g = g_Wc;
#pragma unroll
        for (int j = 0; j < 24; j++) {           // 6144 cp16
            int c = tid + j * 256;
            CP16(sa + (uint32_t)c * 16, g + c * 4);
        }
        const uint32_t sb = smem_u32(as);
#pragma unroll
        for (int j = 0; j < 12; j++) {           // 3072 cp16 (192 per row)
            int c = tid + j * 256;
            int row = c / 192, ch = c % 192;
            const float* src = te + ((size_t)batch * S_ + pos[r0 + row]) * H_ + ch * 4;
            CP16(sb + (uint32_t)(row * H_ + ch * 4) * 4, src);
        }
        CP_COMMIT();
    }

    // pq for this batch, overlapped with staging (global/L2 reads only)
    {
        const float* wcb = g_Wc + H_ * 32;
        const float* prow = pooler + (size_t)batch * H_;
        const int kb = wid * 96;
        float pacc = 0.f;
#pragma unroll
        for (int kk = 0; kk < 96; kk += 4) {
            float4 a4 = *(const float4*)&prow[kb + kk];
            pacc = fmaf(a4.x, wcb[(kb + kk + 0) * 32 + lane], pacc);
            pacc = fmaf(a4.y, wcb[(kb + kk + 1) * 32 + lane], pacc);
            pacc = fmaf(a4.z, wcb[(kb + kk + 2) * 32 + lane], pacc);
            pacc = fmaf(a4.w, wcb[(kb + kk + 3) * 32 + lane], pacc);
        }
        pqs[wid][lane] = pacc;
    }
    CP_WAIT0();
    __syncthreads();
    float pqv = g_bc[lane];
#pragma unroll
    for (int w = 0; w < 8; w++) pqv += pqs[w][lane];   // fixed order

    // 2 rows per warp, 2 k-partials each (4 independent chains)
    const float* a0 = as + (wid * 2 + 0) * H_;
    const float* a1 = as + (wid * 2 + 1) * H_;
    float p00 = 0.f, p01 = 0.f, p10 = 0.f, p11 = 0.f;
#pragma unroll 4
    for (int k = 0; k < H_; k += 8) {
        float4 u0 = *(const float4*)&a0[k];
        float4 u1 = *(const float4*)&a0[k + 4];
        float4 v0 = *(const float4*)&a1[k];
        float4 v1 = *(const float4*)&a1[k + 4];
        float w0 = wct[(k + 0) * 32 + lane];
        float w1 = wct[(k + 1) * 32 + lane];
        float w2 = wct[(k + 2) * 32 + lane];
        float w3 = wct[(k + 3) * 32 + lane];
        float w4 = wct[(k + 4) * 32 + lane];
        float w5 = wct[(k + 5) * 32 + lane];
        float w6 = wct[(k + 6) * 32 + lane];
        float w7 = wct[(k + 7) * 32 + lane];
        p00 = fmaf(u0.x, w0, p00); p00 = fmaf(u0.y, w1, p00);
        p00 = fmaf(u0.z, w2, p00); p00 = fmaf(u0.w, w3, p00);
        p01 = fmaf(u1.x, w4, p01); p01 = fmaf(u1.y, w5, p01);
        p01 = fmaf(u1.z, w6, p01); p01 = fmaf(u1.w, w7, p01);
        p10 = fmaf(v0.x, w0, p10); p10 = fmaf(v0.y, w1, p10);
        p10 = fmaf(v0.z, w2, p10); p10 = fmaf(v0.w, w3, p10);
        p11 = fmaf(v1.x, w4, p11); p11 = fmaf(v1.y, w5, p11);
        p11 = fmaf(v1.z, w6, p11); p11 = fmaf(v1.w, w7, p11);
    }
    float acc[2] = { p00 + p01, p10 + p11 };

    const bool active = (lane < L_);
    float st0 = 0.f, st1 = 0.f, st2 = 0.f, st3 = 0.f, st4 = 0.f;
#pragma unroll
    for (int r = 0; r < 2; r++) {
        int gr = r0 + wid * 2 + r;
        float x = acc[r] + pqv;
        float y = active ? labels[(size_t)gr * L_ + lane] : -1.0f;

        unsigned ball_bin  = __ballot_sync(0xffffffffu, active && (x > 0.f));
        unsigned ball_one  = __ballot_sync(0xffffffffu, active && (y > 0.5f));
        unsigned ball_real = __ballot_sync(0xffffffffu, active && (y != -1.0f));

        float sp  = fmaxf(x, 0.f) + log1pf(expf(-fabsf(x)));
        float bce = active ? (sp - x * y) : 0.f;
#pragma unroll
        for (int o = 16; o; o >>= 1) bce += __shfl_xor_sync(0xffffffffu, bce, o);

        if (lane == 0) {
            float mf = (ball_real != 0u) ? 1.f : 0.f;
            int co = __popc(ball_bin);
            int cl = __popc(ball_one);
            float cd = (float)(co - cl);
            bool eq = (mf != 0.f) && (co == 1) && (cl == 1);
            float pd = eq ? (float)(__ffs(ball_bin) - __ffs(ball_one)) : 0.f;
            st0 += mf * bce;
            st1 += mf;
            st2 += mf * cd * cd;
            st3 += pd * pd;
            st4 += eq ? 1.f : 0.f;
        }
    }
    if (lane == 0) {
        sml[wid][0] = st0; sml[wid][1] = st1; sml[wid][2] = st2;
        sml[wid][3] = st3; sml[wid][4] = st4;
    }
    __syncthreads();
    if (tid < 5) {
        float ssum = 0.f;
        for (int w = 0; w < 8; w++) ssum += sml[w][tid];   // fixed order
        g_part[blockIdx.x * 5 + tid] = ssum;
    }

    // ---- last-block final reduction (deterministic fixed-order tree) ----
    __threadfence();
    __syncthreads();
    if (tid == 0) s_done = atomicAdd(&g_done, 1u);
    __syncthreads();
    if (s_done == 127u) {
        __threadfence();
        if (tid < 128)
            for (int c = 0; c < 5; c++) red[tid][c] = g_part[tid * 5 + c];
        __syncthreads();
        for (int st = 64; st > 0; st >>= 1) {
            if (tid < st)
                for (int c = 0; c < 5; c++) red[tid][c] += red[tid + st][c];
            __syncthreads();
        }
        if (tid == 0) {
            float bce_loss   = red[0][0] / (red[0][1] * (float)L_);
            float count_loss = red[0][2] / (float)MROWS;
            float pos_loss   = (red[0][4] > 0.f) ? (red[0][3] / red[0][4]) : 0.f;
            float loss = bce_loss + 10.f * count_loss + 5.f * pos_loss;
            for (int i = 0; i < out_size; i++) out[i] = loss;
        }
    }
}

// ======================= launch =======================
extern "C" void kernel_launch(void* const* d_in, const int* in_sizes, int n_in,
                              void* d_out, int out_size)
{
    const float* te   = (const float*)d_in[0];
    const float* pool = (const float*)d_in[1];
    const int*   pos  = (const int*)  d_in[2];
    const float* lab  = (const float*)d_in[3];
    const float* W1   = (const float*)d_in[4];
    const float* b1   = (const float*)d_in[5];
    const float* W2   = (const float*)d_in[6];
    const float* b2   = (const float*)d_in[7];
    const float* W3   = (const float*)d_in[8];
    const float* b3   = (const float*)d_in[9];

    const int SM_W23  = (512 * 30 + 8 + 8 * 512) * 4;   //  77856
    const int SM_WC   = (FH_ * 32 + 12 * FH_) * 4;      // 180224
    const int SM_MAIN = (H_ * 32 + 16 * H_) * 4;        // 147456

    cudaFuncSetAttribute(k_w23,  cudaFuncAttributeMaxDynamicSharedMemorySize, SM_W23);
    cudaFuncSetAttribute(k_wc,   cudaFuncAttributeMaxDynamicSharedMemorySize, SM_WC);
    cudaFuncSetAttribute(k_main, cudaFuncAttributeMaxDynamicSharedMemorySize, SM_MAIN);

    k_w23<<<FH_ / 8, 512, SM_W23>>>(W2, W3, b2, b3);    // W23, b23 (+reset counter)
    k_wc<<<(2 * H_) / 12, 192, SM_WC>>>(W1, b1);        // Wc, bc
    k_main<<<MROWS / 16, 256, SM_MAIN>>>(te, pos, lab, pool,
                                         (float*)d_out, out_size);
}